// round 1
// baseline (speedup 1.0000x reference)
#include <cuda_runtime.h>
#include <math.h>

// Problem constants
// B=8, S=256, N=256, C=64, NH=8, D=2048
#define BB 8
#define SS 256
#define NN 256
#define CC 64
#define NHH 8
#define DD 2048

// Scratch (device globals; no runtime allocation)
__device__ float g_q [(size_t)BB*NHH*SS*DD];   // [b][h][s][d]
__device__ float g_k [(size_t)BB*NHH*SS*DD];
__device__ float g_vH[(size_t)BB*NHH*SS*DD];
__device__ float g_vV[(size_t)BB*NHH*SS*DD];   // already reoriented to final layout
__device__ float g_inq[BB*NHH*SS];
__device__ float g_ink[BB*NHH*SS];
__device__ float g_sim[(size_t)BB*NHH*SS*SS];
__device__ float g_aH [(size_t)BB*NHH*SS*SS];
__device__ float g_aV [(size_t)BB*NHH*SS*SS];
__device__ float g_x  [(size_t)BB*SS*NN*CC];   // (x_H + x_V) in token layout [b][t][c]

// ---------------------------------------------------------------------------
// Kernel 1: QKV GEMM  Y[T,f] = X[T,:] @ W[f,:] + bias[f], scatter into q/k/vH/vV
// T = b*65536 + s*256 + n ; f in [0,256)
// mapping: g=n>>6 (0:q 1:k 2:vH 3:vV), h=(n>>3)&7, d=(n&7)*256+f
// vV reorientation at write: h2=s>>5, s2=h*32+(d>>6), d2=(s&31)*64+(d&63)
// ---------------------------------------------------------------------------
__global__ __launch_bounds__(256) void k_qkv(const float* __restrict__ X,
                                             const float* __restrict__ W,
                                             const float* __restrict__ bias)
{
    __shared__ float sX[64][65];
    __shared__ float sW[64][65];
    const int tx = threadIdx.x;
    const size_t T0 = (size_t)blockIdx.x * 64;
    const int f0 = blockIdx.y * 64;

    for (int i = tx; i < 1024; i += 256) {
        int r = i >> 4, c4 = (i & 15) << 2;
        float4 xv = *(const float4*)(X + (T0 + r) * 64 + c4);
        sX[r][c4] = xv.x; sX[r][c4+1] = xv.y; sX[r][c4+2] = xv.z; sX[r][c4+3] = xv.w;
        float4 wv = *(const float4*)(W + (size_t)(f0 + r) * 64 + c4);
        sW[r][c4] = wv.x; sW[r][c4+1] = wv.y; sW[r][c4+2] = wv.z; sW[r][c4+3] = wv.w;
    }
    __syncthreads();

    const int tc = tx & 15, ty = tx >> 4;
    float acc[4][4] = {};
#pragma unroll 16
    for (int kk = 0; kk < 64; kk++) {
        float a[4], b[4];
#pragma unroll
        for (int i = 0; i < 4; i++) a[i] = sX[ty*4 + i][kk];
#pragma unroll
        for (int j = 0; j < 4; j++) b[j] = sW[tc*4 + j][kk];
#pragma unroll
        for (int i = 0; i < 4; i++)
#pragma unroll
            for (int j = 0; j < 4; j++) acc[i][j] += a[i] * b[j];
    }

    const int fbase = f0 + tc * 4;
    float4 bv = *(const float4*)(bias + fbase);
#pragma unroll
    for (int i = 0; i < 4; i++) {
        size_t T = T0 + ty*4 + i;
        int b  = (int)(T >> 16);
        int t16 = (int)(T & 65535);
        int s  = t16 >> 8;
        int n  = t16 & 255;
        int g  = n >> 6;
        int hh = (n >> 3) & 7;
        int d0 = ((n & 7) << 8) + fbase;
        float4 val;
        val.x = acc[i][0] + bv.x; val.y = acc[i][1] + bv.y;
        val.z = acc[i][2] + bv.z; val.w = acc[i][3] + bv.w;
        float* dst; size_t idx;
        if (g == 3) {
            int h2 = s >> 5;
            int s2 = hh * 32 + (d0 >> 6);
            int d2 = ((s & 31) << 6) + (d0 & 63);
            dst = g_vV;
            idx = (((size_t)(b*8 + h2) * 256 + s2) << 11) + d2;
        } else {
            dst = (g == 0) ? g_q : (g == 1 ? g_k : g_vH);
            idx = (((size_t)(b*8 + hh) * 256 + s) << 11) + d0;
        }
        *(float4*)(dst + idx) = val;
    }
}

// ---------------------------------------------------------------------------
// Kernel 2: inverse row norms of q and k (rows of 2048)
// ---------------------------------------------------------------------------
__global__ __launch_bounds__(256) void k_norm()
{
    const int row = blockIdx.x;                 // 0..16383
    const float* src = (blockIdx.y == 0 ? g_q : g_k) + (size_t)row * 2048;
    const int tx = threadIdx.x;
    float s = 0.0f;
#pragma unroll
    for (int i = tx; i < 2048; i += 256) { float v = src[i]; s += v * v; }
#pragma unroll
    for (int o = 16; o; o >>= 1) s += __shfl_xor_sync(0xffffffffu, s, o);
    __shared__ float ws[8];
    if ((tx & 31) == 0) ws[tx >> 5] = s;
    __syncthreads();
    if (tx == 0) {
        float t = 0.0f;
#pragma unroll
        for (int i = 0; i < 8; i++) t += ws[i];
        float inv = 1.0f / fmaxf(sqrtf(t), 1e-12f);
        (blockIdx.y == 0 ? g_inq : g_ink)[row] = inv;
    }
}

// ---------------------------------------------------------------------------
// Kernel 3: sim = (q @ k^T) * invq * invk per (b,h). 64 GEMMs 256x256x2048.
// grid (64, 4, 4), tile 64x64, K chunk 32
// ---------------------------------------------------------------------------
__global__ __launch_bounds__(256) void k_sim()
{
    __shared__ float sQ[64][33];
    __shared__ float sK[64][33];
    const int tx = threadIdx.x;
    const int bh = blockIdx.x;
    const float* Q = g_q + ((size_t)bh * 256 + blockIdx.y * 64) * 2048;
    const float* K = g_k + ((size_t)bh * 256 + blockIdx.z * 64) * 2048;
    const int ty = tx >> 4, tc = tx & 15;
    float acc[4][4] = {};

    for (int k0 = 0; k0 < 2048; k0 += 32) {
        for (int i = tx; i < 512; i += 256) {
            int r = i >> 3, c4 = (i & 7) << 2;
            float4 q4 = *(const float4*)(Q + (size_t)r * 2048 + k0 + c4);
            sQ[r][c4] = q4.x; sQ[r][c4+1] = q4.y; sQ[r][c4+2] = q4.z; sQ[r][c4+3] = q4.w;
            float4 k4 = *(const float4*)(K + (size_t)r * 2048 + k0 + c4);
            sK[r][c4] = k4.x; sK[r][c4+1] = k4.y; sK[r][c4+2] = k4.z; sK[r][c4+3] = k4.w;
        }
        __syncthreads();
#pragma unroll
        for (int kk = 0; kk < 32; kk++) {
            float a[4], b[4];
#pragma unroll
            for (int i = 0; i < 4; i++) a[i] = sQ[ty*4 + i][kk];
#pragma unroll
            for (int j = 0; j < 4; j++) b[j] = sK[tc*4 + j][kk];
#pragma unroll
            for (int i = 0; i < 4; i++)
#pragma unroll
                for (int j = 0; j < 4; j++) acc[i][j] += a[i] * b[j];
        }
        __syncthreads();
    }

    const int srow0 = blockIdx.y * 64 + ty * 4;
    const int tcol0 = blockIdx.z * 64 + tc * 4;
    float iq[4], ik[4];
#pragma unroll
    for (int i = 0; i < 4; i++) iq[i] = g_inq[bh * 256 + srow0 + i];
#pragma unroll
    for (int j = 0; j < 4; j++) ik[j] = g_ink[bh * 256 + tcol0 + j];
#pragma unroll
    for (int i = 0; i < 4; i++) {
        float4 o;
        o.x = acc[i][0] * iq[i] * ik[0];
        o.y = acc[i][1] * iq[i] * ik[1];
        o.z = acc[i][2] * iq[i] * ik[2];
        o.w = acc[i][3] * iq[i] * ik[3];
        *(float4*)(g_sim + ((size_t)bh * 256 + srow0 + i) * 256 + tcol0) = o;
    }
}

// ---------------------------------------------------------------------------
// Kernel 4: dual softmax (temperature1 / temperature2) over rows of 256
// ---------------------------------------------------------------------------
__global__ __launch_bounds__(256) void k_softmax(const float* __restrict__ t1p,
                                                 const float* __restrict__ t2p)
{
    __shared__ float red1[8], red2[8];
    const int row = blockIdx.x, tx = threadIdx.x;
    const int h = (row >> 8) & 7;
    const float T1 = t1p[h], T2 = t2p[h];
    float v = g_sim[(size_t)row * 256 + tx];
    float a = v * T1, c = v * T2;

    float m1 = a, m2 = c;
#pragma unroll
    for (int o = 16; o; o >>= 1) {
        m1 = fmaxf(m1, __shfl_xor_sync(0xffffffffu, m1, o));
        m2 = fmaxf(m2, __shfl_xor_sync(0xffffffffu, m2, o));
    }
    if ((tx & 31) == 0) { red1[tx >> 5] = m1; red2[tx >> 5] = m2; }
    __syncthreads();
    m1 = red1[0]; m2 = red2[0];
#pragma unroll
    for (int i = 1; i < 8; i++) { m1 = fmaxf(m1, red1[i]); m2 = fmaxf(m2, red2[i]); }

    float e1 = expf(a - m1), e2 = expf(c - m2);
    float s1 = e1, s2 = e2;
#pragma unroll
    for (int o = 16; o; o >>= 1) {
        s1 += __shfl_xor_sync(0xffffffffu, s1, o);
        s2 += __shfl_xor_sync(0xffffffffu, s2, o);
    }
    __syncthreads();
    if ((tx & 31) == 0) { red1[tx >> 5] = s1; red2[tx >> 5] = s2; }
    __syncthreads();
    s1 = 0.0f; s2 = 0.0f;
#pragma unroll
    for (int i = 0; i < 8; i++) { s1 += red1[i]; s2 += red2[i]; }

    g_aH[(size_t)row * 256 + tx] = e1 / s1;
    g_aV[(size_t)row * 256 + tx] = e2 / s2;
}

// ---------------------------------------------------------------------------
// Kernel 5: x = attnH @ vH + attnV @ vV, written in token layout [b][t][c]
// token t = s*256 + h*32 + (d>>6), c = d&63.
// grid (64, 4, 32): per (b,h), s-tile 64, d-tile 64. K = 256 (chunks of 32).
// ---------------------------------------------------------------------------
__global__ __launch_bounds__(256) void k_pv()
{
    __shared__ float sAH[64][33];
    __shared__ float sAV[64][33];
    __shared__ float sVH[32][64];
    __shared__ float sVV[32][64];
    const int tx = threadIdx.x;
    const int bh = blockIdx.x;
    const int b = bh >> 3, h = bh & 7;
    const float* AH = g_aH + ((size_t)bh * 256 + blockIdx.y * 64) * 256;
    const float* AV = g_aV + ((size_t)bh * 256 + blockIdx.y * 64) * 256;
    const float* VH = g_vH + (size_t)bh * 256 * 2048 + blockIdx.z * 64;
    const float* VV = g_vV + (size_t)bh * 256 * 2048 + blockIdx.z * 64;
    const int ty = tx >> 4, tc = tx & 15;
    float acc[4][4] = {};

    for (int k0 = 0; k0 < 256; k0 += 32) {
        for (int i = tx; i < 512; i += 256) {
            int r = i >> 3, c4 = (i & 7) << 2;
            float4 a4 = *(const float4*)(AH + (size_t)r * 256 + k0 + c4);
            sAH[r][c4] = a4.x; sAH[r][c4+1] = a4.y; sAH[r][c4+2] = a4.z; sAH[r][c4+3] = a4.w;
            float4 v4 = *(const float4*)(AV + (size_t)r * 256 + k0 + c4);
            sAV[r][c4] = v4.x; sAV[r][c4+1] = v4.y; sAV[r][c4+2] = v4.z; sAV[r][c4+3] = v4.w;
        }
        for (int i = tx; i < 512; i += 256) {
            int r = i >> 4, c4 = (i & 15) << 2;
            *(float4*)&sVH[r][c4] = *(const float4*)(VH + (size_t)(k0 + r) * 2048 + c4);
            *(float4*)&sVV[r][c4] = *(const float4*)(VV + (size_t)(k0 + r) * 2048 + c4);
        }
        __syncthreads();
#pragma unroll
        for (int kk = 0; kk < 32; kk++) {
            float aH[4], aV[4];
#pragma unroll
            for (int i = 0; i < 4; i++) { aH[i] = sAH[ty*4 + i][kk]; aV[i] = sAV[ty*4 + i][kk]; }
            float4 bH = *(float4*)&sVH[kk][tc << 2];
            float4 bV = *(float4*)&sVV[kk][tc << 2];
#pragma unroll
            for (int i = 0; i < 4; i++) {
                acc[i][0] += aH[i] * bH.x + aV[i] * bV.x;
                acc[i][1] += aH[i] * bH.y + aV[i] * bV.y;
                acc[i][2] += aH[i] * bH.z + aV[i] * bV.z;
                acc[i][3] += aH[i] * bH.w + aV[i] * bV.w;
            }
        }
        __syncthreads();
    }

#pragma unroll
    for (int i = 0; i < 4; i++) {
        int s = blockIdx.y * 64 + ty * 4 + i;
        size_t tok = (size_t)b * 65536 + (size_t)s * 256 + h * 32 + blockIdx.z;
        float4 o;
        o.x = acc[i][0]; o.y = acc[i][1]; o.z = acc[i][2]; o.w = acc[i][3];
        *(float4*)(g_x + tok * 64 + (tc << 2)) = o;
    }
}

// ---------------------------------------------------------------------------
// Kernel 6: output projection  out[T,c] = x[T,:] @ proj_w[c,:] + proj_b[c]
// ---------------------------------------------------------------------------
__global__ __launch_bounds__(256) void k_proj(const float* __restrict__ Wp,
                                              const float* __restrict__ bp,
                                              float* __restrict__ out)
{
    __shared__ float sX[64][65];
    __shared__ float sW[64][65];
    const int tx = threadIdx.x;
    const size_t T0 = (size_t)blockIdx.x * 64;

    for (int i = tx; i < 1024; i += 256) {
        int r = i >> 4, c4 = (i & 15) << 2;
        float4 xv = *(const float4*)(g_x + (T0 + r) * 64 + c4);
        sX[r][c4] = xv.x; sX[r][c4+1] = xv.y; sX[r][c4+2] = xv.z; sX[r][c4+3] = xv.w;
        float4 wv = *(const float4*)(Wp + (size_t)r * 64 + c4);
        sW[r][c4] = wv.x; sW[r][c4+1] = wv.y; sW[r][c4+2] = wv.z; sW[r][c4+3] = wv.w;
    }
    __syncthreads();

    const int tc = tx & 15, ty = tx >> 4;
    float acc[4][4] = {};
#pragma unroll 16
    for (int kk = 0; kk < 64; kk++) {
        float a[4], b[4];
#pragma unroll
        for (int i = 0; i < 4; i++) a[i] = sX[ty*4 + i][kk];
#pragma unroll
        for (int j = 0; j < 4; j++) b[j] = sW[tc*4 + j][kk];
#pragma unroll
        for (int i = 0; i < 4; i++)
#pragma unroll
            for (int j = 0; j < 4; j++) acc[i][j] += a[i] * b[j];
    }

    float4 bv = *(const float4*)(bp + (tc << 2));
#pragma unroll
    for (int i = 0; i < 4; i++) {
        size_t T = T0 + ty*4 + i;
        float4 o;
        o.x = acc[i][0] + bv.x; o.y = acc[i][1] + bv.y;
        o.z = acc[i][2] + bv.z; o.w = acc[i][3] + bv.w;
        *(float4*)(out + T * 64 + (tc << 2)) = o;
    }
}

// ---------------------------------------------------------------------------
extern "C" void kernel_launch(void* const* d_in, const int* in_sizes, int n_in,
                              void* d_out, int out_size)
{
    const float* x      = (const float*)d_in[0];
    const float* qkv_w  = (const float*)d_in[1];
    const float* qkv_b  = (const float*)d_in[2];
    const float* proj_w = (const float*)d_in[3];
    const float* proj_b = (const float*)d_in[4];
    const float* t1     = (const float*)d_in[5];
    const float* t2     = (const float*)d_in[6];
    float* out          = (float*)d_out;

    k_qkv<<<dim3(8192, 4), 256>>>(x, qkv_w, qkv_b);
    k_norm<<<dim3(16384, 2), 256>>>();
    k_sim<<<dim3(64, 4, 4), 256>>>();
    k_softmax<<<16384, 256>>>(t1, t2);
    k_pv<<<dim3(64, 4, 32), 256>>>();
    k_proj<<<8192, 256>>>(proj_w, proj_b, out);
}

// round 3
// speedup vs baseline: 2.2614x; 2.2614x over previous
#include <cuda_runtime.h>
#include <math.h>

// B=8, S=256, N=256, C=64, NH=8, D=2048
#define BB 8
#define SS 256
#define DD 2048

// Scratch (device globals)
__device__ float g_q [(size_t)BB*8*SS*DD];
__device__ float g_k [(size_t)BB*8*SS*DD];
__device__ float g_vH[(size_t)BB*8*SS*DD];
__device__ float g_vV[(size_t)BB*8*SS*DD];
__device__ float g_inq[BB*8*SS];
__device__ float g_ink[BB*8*SS];
__device__ float g_sim[(size_t)BB*8*SS*SS];
__device__ float g_aH [(size_t)BB*8*SS*SS];
__device__ float g_aV [(size_t)BB*8*SS*SS];
__device__ float g_x  [(size_t)BB*SS*256*64];

__device__ __forceinline__ unsigned f2tf(float f) {
    unsigned u;
    asm("cvt.rna.tf32.f32 %0, %1;" : "=r"(u) : "f"(f));
    return u;
}

__device__ __forceinline__ void mma_tf32(float* c, unsigned a0, unsigned a1,
                                         unsigned a2, unsigned a3,
                                         unsigned b0, unsigned b1) {
    asm volatile(
        "mma.sync.aligned.m16n8k8.row.col.f32.tf32.tf32.f32 "
        "{%0,%1,%2,%3}, {%4,%5,%6,%7}, {%8,%9}, {%0,%1,%2,%3};"
        : "+f"(c[0]), "+f"(c[1]), "+f"(c[2]), "+f"(c[3])
        : "r"(a0), "r"(a1), "r"(a2), "r"(a3), "r"(b0), "r"(b1));
}

// ---------------------------------------------------------------------------
// Kernel 1: QKV GEMM (tf32 MMA). Y[T,f] = X[T,:] @ W[f,:] + bias[f], scattered.
// BM=128, BN=128, KC=32, K=64. grid (4096, 2), 256 threads (8 warps 2x4).
// ---------------------------------------------------------------------------
__global__ __launch_bounds__(256) void k_qkv(const float* __restrict__ X,
                                             const float* __restrict__ W,
                                             const float* __restrict__ bias)
{
    __shared__ unsigned sA[128][36];
    __shared__ unsigned sB[128][36];
    const int t = threadIdx.x;
    const int lane = t & 31, warp = t >> 5;
    const int m0 = (warp >> 2) * 64, n0 = (warp & 3) * 32;
    const int r = lane >> 2, c = lane & 3;
    const size_t T0 = (size_t)blockIdx.x * 128;
    const int f0 = blockIdx.y * 128;

    float acc[4][4][4] = {};

    for (int k0 = 0; k0 < 64; k0 += 32) {
#pragma unroll
        for (int p = 0; p < 4; p++) {
            int row = (t >> 3) + p * 32, c4 = (t & 7) << 2;
            float4 v = *(const float4*)(X + (T0 + row) * 64 + k0 + c4);
            sA[row][c4] = f2tf(v.x); sA[row][c4+1] = f2tf(v.y);
            sA[row][c4+2] = f2tf(v.z); sA[row][c4+3] = f2tf(v.w);
            float4 w4 = *(const float4*)(W + (size_t)(f0 + row) * 64 + k0 + c4);
            sB[row][c4] = f2tf(w4.x); sB[row][c4+1] = f2tf(w4.y);
            sB[row][c4+2] = f2tf(w4.z); sB[row][c4+3] = f2tf(w4.w);
        }
        __syncthreads();
#pragma unroll
        for (int kk = 0; kk < 32; kk += 8) {
            unsigned af[4][4], bf[4][2];
#pragma unroll
            for (int mt = 0; mt < 4; mt++) {
                int mr = m0 + mt * 16 + r;
                af[mt][0] = sA[mr][kk+c];     af[mt][1] = sA[mr+8][kk+c];
                af[mt][2] = sA[mr][kk+c+4];   af[mt][3] = sA[mr+8][kk+c+4];
            }
#pragma unroll
            for (int nt = 0; nt < 4; nt++) {
                int nr = n0 + nt * 8 + r;
                bf[nt][0] = sB[nr][kk+c]; bf[nt][1] = sB[nr][kk+c+4];
            }
#pragma unroll
            for (int mt = 0; mt < 4; mt++)
#pragma unroll
                for (int nt = 0; nt < 4; nt++)
                    mma_tf32(acc[mt][nt], af[mt][0], af[mt][1], af[mt][2], af[mt][3],
                             bf[nt][0], bf[nt][1]);
        }
        __syncthreads();
    }

    // epilogue: bias add + scatter (q/k/vH/vV with v_V reorientation)
#pragma unroll
    for (int mt = 0; mt < 4; mt++) {
#pragma unroll
        for (int rr = 0; rr < 2; rr++) {
            size_t T = T0 + m0 + mt * 16 + r + rr * 8;
            int b = (int)(T >> 16);
            int s = (int)((T >> 8) & 255);
            int n = (int)(T & 255);
            int g = n >> 6;
            int h = (n >> 3) & 7;
#pragma unroll
            for (int nt = 0; nt < 4; nt++) {
                int f = f0 + n0 + nt * 8 + 2 * c;
                float2 bv = *(const float2*)(bias + f);
                float2 val;
                val.x = acc[mt][nt][rr*2]   + bv.x;
                val.y = acc[mt][nt][rr*2+1] + bv.y;
                int d0 = ((n & 7) << 8) + f;
                float* dst; size_t idx;
                if (g == 3) {
                    int h2 = s >> 5;
                    int s2 = h * 32 + (d0 >> 6);
                    int d2 = ((s & 31) << 6) + (d0 & 63);
                    dst = g_vV;
                    idx = (((size_t)(b * 8 + h2) * 256 + s2) << 11) + d2;
                } else {
                    dst = (g == 0) ? g_q : (g == 1 ? g_k : g_vH);
                    idx = (((size_t)(b * 8 + h) * 256 + s) << 11) + d0;
                }
                *(float2*)(dst + idx) = val;
            }
        }
    }
}

// ---------------------------------------------------------------------------
// Kernel 2: inverse row norms of q and k
// ---------------------------------------------------------------------------
__global__ __launch_bounds__(256) void k_norm()
{
    const int row = blockIdx.x;
    const float* src = (blockIdx.y == 0 ? g_q : g_k) + (size_t)row * 2048;
    const int tx = threadIdx.x;
    float s = 0.0f;
#pragma unroll
    for (int i = tx; i < 2048; i += 256) { float v = src[i]; s += v * v; }
#pragma unroll
    for (int o = 16; o; o >>= 1) s += __shfl_xor_sync(0xffffffffu, s, o);
    __shared__ float ws[8];
    if ((tx & 31) == 0) ws[tx >> 5] = s;
    __syncthreads();
    if (tx == 0) {
        float tt = 0.0f;
#pragma unroll
        for (int i = 0; i < 8; i++) tt += ws[i];
        (blockIdx.y == 0 ? g_inq : g_ink)[row] = 1.0f / fmaxf(sqrtf(tt), 1e-12f);
    }
}

// ---------------------------------------------------------------------------
// Kernel 3: sim = (q @ k^T) * invq * invk (tf32 MMA). grid (64,2,2).
// ---------------------------------------------------------------------------
__global__ __launch_bounds__(256) void k_sim()
{
    __shared__ unsigned sA[128][36];
    __shared__ unsigned sB[128][36];
    const int t = threadIdx.x;
    const int lane = t & 31, warp = t >> 5;
    const int m0 = (warp >> 2) * 64, n0 = (warp & 3) * 32;
    const int r = lane >> 2, c = lane & 3;
    const int bh = blockIdx.x;
    const float* Q = g_q + ((size_t)bh * 256 + blockIdx.y * 128) * 2048;
    const float* K = g_k + ((size_t)bh * 256 + blockIdx.z * 128) * 2048;

    float acc[4][4][4] = {};

    for (int k0 = 0; k0 < 2048; k0 += 32) {
#pragma unroll
        for (int p = 0; p < 4; p++) {
            int row = (t >> 3) + p * 32, c4 = (t & 7) << 2;
            float4 q4 = *(const float4*)(Q + (size_t)row * 2048 + k0 + c4);
            sA[row][c4] = f2tf(q4.x); sA[row][c4+1] = f2tf(q4.y);
            sA[row][c4+2] = f2tf(q4.z); sA[row][c4+3] = f2tf(q4.w);
            float4 k4 = *(const float4*)(K + (size_t)row * 2048 + k0 + c4);
            sB[row][c4] = f2tf(k4.x); sB[row][c4+1] = f2tf(k4.y);
            sB[row][c4+2] = f2tf(k4.z); sB[row][c4+3] = f2tf(k4.w);
        }
        __syncthreads();
#pragma unroll
        for (int kk = 0; kk < 32; kk += 8) {
            unsigned af[4][4], bf[4][2];
#pragma unroll
            for (int mt = 0; mt < 4; mt++) {
                int mr = m0 + mt * 16 + r;
                af[mt][0] = sA[mr][kk+c];   af[mt][1] = sA[mr+8][kk+c];
                af[mt][2] = sA[mr][kk+c+4]; af[mt][3] = sA[mr+8][kk+c+4];
            }
#pragma unroll
            for (int nt = 0; nt < 4; nt++) {
                int nr = n0 + nt * 8 + r;
                bf[nt][0] = sB[nr][kk+c]; bf[nt][1] = sB[nr][kk+c+4];
            }
#pragma unroll
            for (int mt = 0; mt < 4; mt++)
#pragma unroll
                for (int nt = 0; nt < 4; nt++)
                    mma_tf32(acc[mt][nt], af[mt][0], af[mt][1], af[mt][2], af[mt][3],
                             bf[nt][0], bf[nt][1]);
        }
        __syncthreads();
    }

#pragma unroll
    for (int mt = 0; mt < 4; mt++) {
        int row = blockIdx.y * 128 + m0 + mt * 16 + r;
        float iq0 = g_inq[bh * 256 + row];
        float iq1 = g_inq[bh * 256 + row + 8];
#pragma unroll
        for (int nt = 0; nt < 4; nt++) {
            int col = blockIdx.z * 128 + n0 + nt * 8 + 2 * c;
            float2 ik2 = *(const float2*)(g_ink + bh * 256 + col);
            float2 o0, o1;
            o0.x = acc[mt][nt][0] * iq0 * ik2.x;
            o0.y = acc[mt][nt][1] * iq0 * ik2.y;
            o1.x = acc[mt][nt][2] * iq1 * ik2.x;
            o1.y = acc[mt][nt][3] * iq1 * ik2.y;
            *(float2*)(g_sim + ((size_t)bh * 256 + row) * 256 + col) = o0;
            *(float2*)(g_sim + ((size_t)bh * 256 + row + 8) * 256 + col) = o1;
        }
    }
}

// ---------------------------------------------------------------------------
// Kernel 4: dual softmax over rows of 256
// ---------------------------------------------------------------------------
__global__ __launch_bounds__(256) void k_softmax(const float* __restrict__ t1p,
                                                 const float* __restrict__ t2p)
{
    __shared__ float red1[8], red2[8];
    const int row = blockIdx.x, tx = threadIdx.x;
    const int h = (row >> 8) & 7;
    const float T1 = t1p[h], T2 = t2p[h];
    float v = g_sim[(size_t)row * 256 + tx];
    float a = v * T1, cc = v * T2;

    float m1 = a, m2 = cc;
#pragma unroll
    for (int o = 16; o; o >>= 1) {
        m1 = fmaxf(m1, __shfl_xor_sync(0xffffffffu, m1, o));
        m2 = fmaxf(m2, __shfl_xor_sync(0xffffffffu, m2, o));
    }
    if ((tx & 31) == 0) { red1[tx >> 5] = m1; red2[tx >> 5] = m2; }
    __syncthreads();
    m1 = red1[0]; m2 = red2[0];
#pragma unroll
    for (int i = 1; i < 8; i++) { m1 = fmaxf(m1, red1[i]); m2 = fmaxf(m2, red2[i]); }

    float e1 = expf(a - m1), e2 = expf(cc - m2);
    float s1 = e1, s2 = e2;
#pragma unroll
    for (int o = 16; o; o >>= 1) {
        s1 += __shfl_xor_sync(0xffffffffu, s1, o);
        s2 += __shfl_xor_sync(0xffffffffu, s2, o);
    }
    __syncthreads();
    if ((tx & 31) == 0) { red1[tx >> 5] = s1; red2[tx >> 5] = s2; }
    __syncthreads();
    s1 = 0.0f; s2 = 0.0f;
#pragma unroll
    for (int i = 0; i < 8; i++) { s1 += red1[i]; s2 += red2[i]; }

    g_aH[(size_t)row * 256 + tx] = e1 / s1;
    g_aV[(size_t)row * 256 + tx] = e2 / s2;
}

// ---------------------------------------------------------------------------
// Kernel 5: x = attnH @ vH + attnV @ vV as one K=512 concat GEMM (tf32 MMA).
// grid (64, 2, 16). Output written directly in token layout.
// ---------------------------------------------------------------------------
__global__ __launch_bounds__(256) void k_pv()
{
    __shared__ unsigned sA[128][36];
    __shared__ unsigned sB[32][136];
    const int t = threadIdx.x;
    const int lane = t & 31, warp = t >> 5;
    const int m0 = (warp >> 2) * 64, n0 = (warp & 3) * 32;
    const int r = lane >> 2, c = lane & 3;
    const int bh = blockIdx.x;

    float acc[4][4][4] = {};

    for (int k0 = 0; k0 < 512; k0 += 32) {
        const float* Ab; const float* Bb;
        if (k0 < 256) {
            Ab = g_aH + ((size_t)bh * 256 + blockIdx.y * 128) * 256 + k0;
            Bb = g_vH + (size_t)bh * 524288 + (size_t)k0 * 2048 + blockIdx.z * 128;
        } else {
            Ab = g_aV + ((size_t)bh * 256 + blockIdx.y * 128) * 256 + (k0 - 256);
            Bb = g_vV + (size_t)bh * 524288 + (size_t)(k0 - 256) * 2048 + blockIdx.z * 128;
        }
#pragma unroll
        for (int p = 0; p < 4; p++) {
            int row = (t >> 3) + p * 32, c4 = (t & 7) << 2;
            float4 a4 = *(const float4*)(Ab + (size_t)row * 256 + c4);
            sA[row][c4] = f2tf(a4.x); sA[row][c4+1] = f2tf(a4.y);
            sA[row][c4+2] = f2tf(a4.z); sA[row][c4+3] = f2tf(a4.w);
        }
#pragma unroll
        for (int p = 0; p < 4; p++) {
            int row = (t >> 5) + p * 8, c4 = (t & 31) << 2;
            float4 v4 = *(const float4*)(Bb + (size_t)row * 2048 + c4);
            sB[row][c4] = f2tf(v4.x); sB[row][c4+1] = f2tf(v4.y);
            sB[row][c4+2] = f2tf(v4.z); sB[row][c4+3] = f2tf(v4.w);
        }
        __syncthreads();
#pragma unroll
        for (int kk = 0; kk < 32; kk += 8) {
            unsigned af[4][4], bf[4][2];
#pragma unroll
            for (int mt = 0; mt < 4; mt++) {
                int mr = m0 + mt * 16 + r;
                af[mt][0] = sA[mr][kk+c];   af[mt][1] = sA[mr+8][kk+c];
                af[mt][2] = sA[mr][kk+c+4]; af[mt][3] = sA[mr+8][kk+c+4];
            }
#pragma unroll
            for (int nt = 0; nt < 4; nt++) {
                int nc = n0 + nt * 8 + r;
                bf[nt][0] = sB[kk+c][nc]; bf[nt][1] = sB[kk+c+4][nc];
            }
#pragma unroll
            for (int mt = 0; mt < 4; mt++)
#pragma unroll
                for (int nt = 0; nt < 4; nt++)
                    mma_tf32(acc[mt][nt], af[mt][0], af[mt][1], af[mt][2], af[mt][3],
                             bf[nt][0], bf[nt][1]);
        }
        __syncthreads();
    }

    const int b = bh >> 3, h = bh & 7;
#pragma unroll
    for (int mt = 0; mt < 4; mt++) {
#pragma unroll
        for (int rr = 0; rr < 2; rr++) {
            int s = blockIdx.y * 128 + m0 + mt * 16 + r + rr * 8;
#pragma unroll
            for (int nt = 0; nt < 4; nt++) {
                int d = blockIdx.z * 128 + n0 + nt * 8 + 2 * c;
                size_t tok = (size_t)b * 65536 + (size_t)s * 256 + h * 32 + (d >> 6);
                float2 o;
                o.x = acc[mt][nt][rr*2];
                o.y = acc[mt][nt][rr*2+1];
                *(float2*)(g_x + tok * 64 + (d & 63)) = o;
            }
        }
    }
}

// ---------------------------------------------------------------------------
// Kernel 6: output projection (tf32 MMA). BM=128, BN=64. grid 4096.
// ---------------------------------------------------------------------------
__global__ __launch_bounds__(256) void k_proj(const float* __restrict__ Wp,
                                              const float* __restrict__ bp,
                                              float* __restrict__ out)
{
    __shared__ unsigned sA[128][36];
    __shared__ unsigned sB[64][36];
    const int t = threadIdx.x;
    const int lane = t & 31, warp = t >> 5;
    const int m0 = (warp >> 1) * 32, n0 = (warp & 1) * 32;
    const int r = lane >> 2, c = lane & 3;
    const size_t T0 = (size_t)blockIdx.x * 128;

    float acc[2][4][4] = {};

    for (int k0 = 0; k0 < 64; k0 += 32) {
#pragma unroll
        for (int p = 0; p < 4; p++) {
            int row = (t >> 3) + p * 32, c4 = (t & 7) << 2;
            float4 v = *(const float4*)(g_x + (T0 + row) * 64 + k0 + c4);
            sA[row][c4] = f2tf(v.x); sA[row][c4+1] = f2tf(v.y);
            sA[row][c4+2] = f2tf(v.z); sA[row][c4+3] = f2tf(v.w);
        }
#pragma unroll
        for (int p = 0; p < 2; p++) {
            int row = (t >> 3) + p * 32, c4 = (t & 7) << 2;
            if (row < 64) {
                float4 w4 = *(const float4*)(Wp + (size_t)row * 64 + k0 + c4);
                sB[row][c4] = f2tf(w4.x); sB[row][c4+1] = f2tf(w4.y);
                sB[row][c4+2] = f2tf(w4.z); sB[row][c4+3] = f2tf(w4.w);
            }
        }
        __syncthreads();
#pragma unroll
        for (int kk = 0; kk < 32; kk += 8) {
            unsigned af[2][4], bf[4][2];
#pragma unroll
            for (int mt = 0; mt < 2; mt++) {
                int mr = m0 + mt * 16 + r;
                af[mt][0] = sA[mr][kk+c];   af[mt][1] = sA[mr+8][kk+c];
                af[mt][2] = sA[mr][kk+c+4]; af[mt][3] = sA[mr+8][kk+c+4];
            }
#pragma unroll
            for (int nt = 0; nt < 4; nt++) {
                int nr = n0 + nt * 8 + r;
                bf[nt][0] = sB[nr][kk+c]; bf[nt][1] = sB[nr][kk+c+4];
            }
#pragma unroll
            for (int mt = 0; mt < 2; mt++)
#pragma unroll
                for (int nt = 0; nt < 4; nt++)
                    mma_tf32(acc[mt][nt], af[mt][0], af[mt][1], af[mt][2], af[mt][3],
                             bf[nt][0], bf[nt][1]);
        }
        __syncthreads();
    }

#pragma unroll
    for (int mt = 0; mt < 2; mt++) {
#pragma unroll
        for (int rr = 0; rr < 2; rr++) {
            size_t T = T0 + m0 + mt * 16 + r + rr * 8;
#pragma unroll
            for (int nt = 0; nt < 4; nt++) {
                int col = n0 + nt * 8 + 2 * c;
                float2 bv = *(const float2*)(bp + col);
                float2 o;
                o.x = acc[mt][nt][rr*2]   + bv.x;
                o.y = acc[mt][nt][rr*2+1] + bv.y;
                *(float2*)(out + T * 64 + col) = o;
            }
        }
    }
}

// ---------------------------------------------------------------------------
extern "C" void kernel_launch(void* const* d_in, const int* in_sizes, int n_in,
                              void* d_out, int out_size)
{
    const float* x      = (const float*)d_in[0];
    const float* qkv_w  = (const float*)d_in[1];
    const float* qkv_b  = (const float*)d_in[2];
    const float* proj_w = (const float*)d_in[3];
    const float* proj_b = (const float*)d_in[4];
    const float* t1     = (const float*)d_in[5];
    const float* t2     = (const float*)d_in[6];
    float* out          = (float*)d_out;

    k_qkv<<<dim3(4096, 2), 256>>>(x, qkv_w, qkv_b);
    k_norm<<<dim3(16384, 2), 256>>>();
    k_sim<<<dim3(64, 2, 2), 256>>>();
    k_softmax<<<16384, 256>>>(t1, t2);
    k_pv<<<dim3(64, 2, 16), 256>>>();
    k_proj<<<4096, 256>>>(proj_w, proj_b, out);
}

// round 4
// speedup vs baseline: 3.5726x; 1.5798x over previous
#include <cuda_runtime.h>
#include <math.h>

// B=8, S=256, N=256, C=64, NH=8, D=2048
#define BB 8
#define SS 256

// Scratch (device globals). q/k/vH/vV/aH/aV are stored pre-rounded to tf32.
__device__ float g_q [(size_t)BB*8*SS*2048];
__device__ float g_k [(size_t)BB*8*SS*2048];
__device__ float g_vH[(size_t)BB*8*SS*2048];
__device__ float g_vV[(size_t)BB*8*SS*2048];
__device__ float g_inq[BB*8*SS];
__device__ float g_ink[BB*8*SS];
__device__ float g_aH [(size_t)BB*8*SS*SS];   // unnormalized exp
__device__ float g_aV [(size_t)BB*8*SS*SS];
__device__ float g_rs1[BB*8*SS];              // softmax row sums
__device__ float g_rs2[BB*8*SS];
__device__ float g_x  [(size_t)BB*SS*256*64];

__device__ __forceinline__ unsigned f2tf(float f) {
    unsigned u;
    asm("cvt.rna.tf32.f32 %0, %1;" : "=r"(u) : "f"(f));
    return u;
}

__device__ __forceinline__ void mma_tf32(float* c, unsigned a0, unsigned a1,
                                         unsigned a2, unsigned a3,
                                         unsigned b0, unsigned b1) {
    asm volatile(
        "mma.sync.aligned.m16n8k8.row.col.f32.tf32.tf32.f32 "
        "{%0,%1,%2,%3}, {%4,%5,%6,%7}, {%8,%9}, {%0,%1,%2,%3};"
        : "+f"(c[0]), "+f"(c[1]), "+f"(c[2]), "+f"(c[3])
        : "r"(a0), "r"(a1), "r"(a2), "r"(a3), "r"(b0), "r"(b1));
}

__device__ __forceinline__ void cpa16(void* s, const void* g) {
    unsigned sa = (unsigned)__cvta_generic_to_shared(s);
    asm volatile("cp.async.cg.shared.global [%0], [%1], 16;" :: "r"(sa), "l"(g));
}
#define CP_COMMIT() asm volatile("cp.async.commit_group;")
#define CP_WAIT1()  asm volatile("cp.async.wait_group 1;")
#define CP_WAIT0()  asm volatile("cp.async.wait_group 0;")

// ---------------------------------------------------------------------------
// Kernel 1: QKV GEMM (tf32 MMA), scatter + tf32-round at write.
// ---------------------------------------------------------------------------
__global__ __launch_bounds__(256) void k_qkv(const float* __restrict__ X,
                                             const float* __restrict__ W,
                                             const float* __restrict__ bias)
{
    __shared__ unsigned sA[128][36];
    __shared__ unsigned sB[128][36];
    const int t = threadIdx.x;
    const int lane = t & 31, warp = t >> 5;
    const int m0 = (warp >> 2) * 64, n0 = (warp & 3) * 32;
    const int r = lane >> 2, cl = lane & 3;
    const size_t T0 = (size_t)blockIdx.x * 128;
    const int f0 = blockIdx.y * 128;

    float acc[4][4][4] = {};

    for (int k0 = 0; k0 < 64; k0 += 32) {
#pragma unroll
        for (int p = 0; p < 4; p++) {
            int row = (t >> 3) + p * 32, c4 = (t & 7) << 2;
            float4 v = *(const float4*)(X + (T0 + row) * 64 + k0 + c4);
            sA[row][c4] = f2tf(v.x); sA[row][c4+1] = f2tf(v.y);
            sA[row][c4+2] = f2tf(v.z); sA[row][c4+3] = f2tf(v.w);
            float4 w4 = *(const float4*)(W + (size_t)(f0 + row) * 64 + k0 + c4);
            sB[row][c4] = f2tf(w4.x); sB[row][c4+1] = f2tf(w4.y);
            sB[row][c4+2] = f2tf(w4.z); sB[row][c4+3] = f2tf(w4.w);
        }
        __syncthreads();
#pragma unroll
        for (int kk = 0; kk < 32; kk += 8) {
            unsigned af[4][4], bf[4][2];
#pragma unroll
            for (int mt = 0; mt < 4; mt++) {
                int mr = m0 + mt * 16 + r;
                af[mt][0] = sA[mr][kk+cl];     af[mt][1] = sA[mr+8][kk+cl];
                af[mt][2] = sA[mr][kk+cl+4];   af[mt][3] = sA[mr+8][kk+cl+4];
            }
#pragma unroll
            for (int nt = 0; nt < 4; nt++) {
                int nr = n0 + nt * 8 + r;
                bf[nt][0] = sB[nr][kk+cl]; bf[nt][1] = sB[nr][kk+cl+4];
            }
#pragma unroll
            for (int mt = 0; mt < 4; mt++)
#pragma unroll
                for (int nt = 0; nt < 4; nt++)
                    mma_tf32(acc[mt][nt], af[mt][0], af[mt][1], af[mt][2], af[mt][3],
                             bf[nt][0], bf[nt][1]);
        }
        __syncthreads();
    }

#pragma unroll
    for (int mt = 0; mt < 4; mt++) {
#pragma unroll
        for (int rr = 0; rr < 2; rr++) {
            size_t T = T0 + m0 + mt * 16 + r + rr * 8;
            int b = (int)(T >> 16);
            int s = (int)((T >> 8) & 255);
            int n = (int)(T & 255);
            int g = n >> 6;
            int h = (n >> 3) & 7;
#pragma unroll
            for (int nt = 0; nt < 4; nt++) {
                int f = f0 + n0 + nt * 8 + 2 * cl;
                float2 bv = *(const float2*)(bias + f);
                float2 val;
                val.x = __uint_as_float(f2tf(acc[mt][nt][rr*2]   + bv.x));
                val.y = __uint_as_float(f2tf(acc[mt][nt][rr*2+1] + bv.y));
                int d0 = ((n & 7) << 8) + f;
                float* dst; size_t idx;
                if (g == 3) {
                    int h2 = s >> 5;
                    int s2 = h * 32 + (d0 >> 6);
                    int d2 = ((s & 31) << 6) + (d0 & 63);
                    dst = g_vV;
                    idx = (((size_t)(b * 8 + h2) * 256 + s2) << 11) + d2;
                } else {
                    dst = (g == 0) ? g_q : (g == 1 ? g_k : g_vH);
                    idx = (((size_t)(b * 8 + h) * 256 + s) << 11) + d0;
                }
                *(float2*)(dst + idx) = val;
            }
        }
    }
}

// ---------------------------------------------------------------------------
// Kernel 2: inverse row norms of q and k
// ---------------------------------------------------------------------------
__global__ __launch_bounds__(256) void k_norm()
{
    const int row = blockIdx.x;
    const float* src = (blockIdx.y == 0 ? g_q : g_k) + (size_t)row * 2048;
    const int tx = threadIdx.x;
    float s = 0.0f;
#pragma unroll
    for (int i = tx; i < 2048; i += 256) { float v = src[i]; s += v * v; }
#pragma unroll
    for (int o = 16; o; o >>= 1) s += __shfl_xor_sync(0xffffffffu, s, o);
    __shared__ float ws[8];
    if ((tx & 31) == 0) ws[tx >> 5] = s;
    __syncthreads();
    if (tx == 0) {
        float tt = 0.0f;
#pragma unroll
        for (int i = 0; i < 8; i++) tt += ws[i];
        (blockIdx.y == 0 ? g_inq : g_ink)[row] = 1.0f / fmaxf(sqrtf(tt), 1e-12f);
    }
}

// ---------------------------------------------------------------------------
// Kernel 3: fused sim + dual softmax. Tile 128x256 (full rows), grid (64,2).
// Writes UNNORMALIZED exp to g_aH/g_aV + row sums to g_rs1/g_rs2.
// cp.async double-buffered, kc=64. Dynamic smem 208896 B.
// ---------------------------------------------------------------------------
#define SIMQ(b,rr,cc) dsm[((b)*128 + (rr))*68 + (cc)]
#define SIMK(b,rr,cc) dsm[2*128*68 + ((b)*256 + (rr))*68 + (cc)]

__global__ __launch_bounds__(256, 1) void k_simsm(const float* __restrict__ t1p,
                                                  const float* __restrict__ t2p)
{
    extern __shared__ unsigned dsm[];
    const int t = threadIdx.x;
    const int lane = t & 31, warp = t >> 5;
    const int m0 = (warp >> 2) * 64;        // 2 m-warps
    const int nwarp = warp & 3;
    const int n0 = nwarp * 64;              // 4 n-warps, 64 cols each
    const int r = lane >> 2, cl = lane & 3;
    const int bh = blockIdx.x, y = blockIdx.y;
    const float* Qb = g_q + ((size_t)bh * 256 + y * 128) * 2048;
    const float* Kb = g_k + (size_t)bh * 256 * 2048;

    float acc[4][8][4] = {};

    // prologue load chunk 0
    {
#pragma unroll
        for (int p = 0; p < 8; p++) {
            int lin = t + p * 256, row = lin >> 4, seg = lin & 15;
            cpa16(&SIMQ(0, row, seg * 4), Qb + (size_t)row * 2048 + seg * 4);
        }
#pragma unroll
        for (int p = 0; p < 16; p++) {
            int lin = t + p * 256, row = lin >> 4, seg = lin & 15;
            cpa16(&SIMK(0, row, seg * 4), Kb + (size_t)row * 2048 + seg * 4);
        }
        CP_COMMIT();
    }

    for (int ch = 0; ch < 32; ch++) {
        if (ch < 31) {
            int nb = (ch + 1) & 1, k0 = (ch + 1) * 64;
#pragma unroll
            for (int p = 0; p < 8; p++) {
                int lin = t + p * 256, row = lin >> 4, seg = lin & 15;
                cpa16(&SIMQ(nb, row, seg * 4), Qb + (size_t)row * 2048 + k0 + seg * 4);
            }
#pragma unroll
            for (int p = 0; p < 16; p++) {
                int lin = t + p * 256, row = lin >> 4, seg = lin & 15;
                cpa16(&SIMK(nb, row, seg * 4), Kb + (size_t)row * 2048 + k0 + seg * 4);
            }
            CP_COMMIT();
            CP_WAIT1();
        } else {
            CP_WAIT0();
        }
        __syncthreads();
        const int buf = ch & 1;
#pragma unroll
        for (int kk = 0; kk < 64; kk += 8) {
            unsigned af[4][4], bf[8][2];
#pragma unroll
            for (int mt = 0; mt < 4; mt++) {
                int mr = m0 + mt * 16 + r;
                af[mt][0] = SIMQ(buf, mr, kk+cl);   af[mt][1] = SIMQ(buf, mr+8, kk+cl);
                af[mt][2] = SIMQ(buf, mr, kk+cl+4); af[mt][3] = SIMQ(buf, mr+8, kk+cl+4);
            }
#pragma unroll
            for (int nt = 0; nt < 8; nt++) {
                int nr = n0 + nt * 8 + r;
                bf[nt][0] = SIMK(buf, nr, kk+cl); bf[nt][1] = SIMK(buf, nr, kk+cl+4);
            }
#pragma unroll
            for (int mt = 0; mt < 4; mt++)
#pragma unroll
                for (int nt = 0; nt < 8; nt++)
                    mma_tf32(acc[mt][nt], af[mt][0], af[mt][1], af[mt][2], af[mt][3],
                             bf[nt][0], bf[nt][1]);
        }
        __syncthreads();
    }

    // ---------------- epilogue: scale + dual softmax ----------------
    const int h = bh & 7;
    const float T1 = t1p[h], T2 = t2p[h];
    const int rowbase = bh * 256 + y * 128;

    float iq[8];
#pragma unroll
    for (int i = 0; i < 8; i++)
        iq[i] = g_inq[rowbase + m0 + (i >> 1) * 16 + (i & 1) * 8 + r];
    float ikv[8][2];
#pragma unroll
    for (int nt = 0; nt < 8; nt++) {
        float2 v2 = *(const float2*)(g_ink + bh * 256 + n0 + nt * 8 + 2 * cl);
        ikv[nt][0] = v2.x; ikv[nt][1] = v2.y;
    }
#pragma unroll
    for (int mt = 0; mt < 4; mt++)
#pragma unroll
        for (int nt = 0; nt < 8; nt++)
#pragma unroll
            for (int rr = 0; rr < 2; rr++) {
                acc[mt][nt][rr*2]   *= iq[mt*2+rr] * ikv[nt][0];
                acc[mt][nt][rr*2+1] *= iq[mt*2+rr] * ikv[nt][1];
            }

    // per-thread row min/max
    float mx[8], mn[8];
#pragma unroll
    for (int i = 0; i < 8; i++) { mx[i] = -3.0e38f; mn[i] = 3.0e38f; }
#pragma unroll
    for (int mt = 0; mt < 4; mt++)
#pragma unroll
        for (int rr = 0; rr < 2; rr++) {
            int i = mt * 2 + rr;
#pragma unroll
            for (int nt = 0; nt < 8; nt++) {
                mx[i] = fmaxf(mx[i], fmaxf(acc[mt][nt][rr*2], acc[mt][nt][rr*2+1]));
                mn[i] = fminf(mn[i], fminf(acc[mt][nt][rr*2], acc[mt][nt][rr*2+1]));
            }
        }
#pragma unroll
    for (int o = 1; o <= 2; o <<= 1)
#pragma unroll
        for (int i = 0; i < 8; i++) {
            mx[i] = fmaxf(mx[i], __shfl_xor_sync(0xffffffffu, mx[i], o));
            mn[i] = fminf(mn[i], __shfl_xor_sync(0xffffffffu, mn[i], o));
        }

    float* sMx = (float*)dsm;          // [128][4]
    float* sMn = (float*)dsm + 512;    // [128][4]
    if (cl == 0) {
#pragma unroll
        for (int i = 0; i < 8; i++) {
            int lr = m0 + (i >> 1) * 16 + (i & 1) * 8 + r;
            sMx[lr * 4 + nwarp] = mx[i];
            sMn[lr * 4 + nwarp] = mn[i];
        }
    }
    __syncthreads();
    float M1[8], M2[8];
#pragma unroll
    for (int i = 0; i < 8; i++) {
        int lr = m0 + (i >> 1) * 16 + (i & 1) * 8 + r;
        float vmx = sMx[lr*4], vmn = sMn[lr*4];
#pragma unroll
        for (int k = 1; k < 4; k++) {
            vmx = fmaxf(vmx, sMx[lr*4+k]);
            vmn = fminf(vmn, sMn[lr*4+k]);
        }
        M1[i] = (T1 >= 0.0f) ? T1 * vmx : T1 * vmn;
        M2[i] = (T2 >= 0.0f) ? T2 * vmx : T2 * vmn;
    }

    // exp + write unnormalized + accumulate sums
    float s1[8] = {}, s2[8] = {};
#pragma unroll
    for (int mt = 0; mt < 4; mt++)
#pragma unroll
        for (int rr = 0; rr < 2; rr++) {
            int i = mt * 2 + rr;
            int lr = m0 + mt * 16 + rr * 8 + r;
            size_t rowoff = (size_t)(rowbase + lr) * 256;
#pragma unroll
            for (int nt = 0; nt < 8; nt++) {
                int col = n0 + nt * 8 + 2 * cl;
                float v0 = acc[mt][nt][rr*2], v1 = acc[mt][nt][rr*2+1];
                float e10 = __expf(v0 * T1 - M1[i]);
                float e11 = __expf(v1 * T1 - M1[i]);
                float e20 = __expf(v0 * T2 - M2[i]);
                float e21 = __expf(v1 * T2 - M2[i]);
                s1[i] += e10 + e11;
                s2[i] += e20 + e21;
                float2 o1, o2;
                o1.x = __uint_as_float(f2tf(e10)); o1.y = __uint_as_float(f2tf(e11));
                o2.x = __uint_as_float(f2tf(e20)); o2.y = __uint_as_float(f2tf(e21));
                *(float2*)(g_aH + rowoff + col) = o1;
                *(float2*)(g_aV + rowoff + col) = o2;
            }
        }
#pragma unroll
    for (int o = 1; o <= 2; o <<= 1)
#pragma unroll
        for (int i = 0; i < 8; i++) {
            s1[i] += __shfl_xor_sync(0xffffffffu, s1[i], o);
            s2[i] += __shfl_xor_sync(0xffffffffu, s2[i], o);
        }
    __syncthreads();
    float* sS1 = (float*)dsm;
    float* sS2 = (float*)dsm + 512;
    if (cl == 0) {
#pragma unroll
        for (int i = 0; i < 8; i++) {
            int lr = m0 + (i >> 1) * 16 + (i & 1) * 8 + r;
            sS1[lr * 4 + nwarp] = s1[i];
            sS2[lr * 4 + nwarp] = s2[i];
        }
    }
    __syncthreads();
    if (nwarp == 0 && cl == 0) {
#pragma unroll
        for (int i = 0; i < 8; i++) {
            int lr = m0 + (i >> 1) * 16 + (i & 1) * 8 + r;
            float tt1 = sS1[lr*4] + sS1[lr*4+1] + sS1[lr*4+2] + sS1[lr*4+3];
            float tt2 = sS2[lr*4] + sS2[lr*4+1] + sS2[lr*4+2] + sS2[lr*4+3];
            g_rs1[rowbase + lr] = tt1;
            g_rs2[rowbase + lr] = tt2;
        }
    }
}

// ---------------------------------------------------------------------------
// Kernel 4: x = (E1 @ vH)/rs1 + (E2 @ vV)/rs2  via concat-K with mid-rescale.
// grid (64, 2, 16). cp.async double-buffered, kc=32. Dyn smem 71680 B.
// ---------------------------------------------------------------------------
#define PVA(b,rr,cc) dsm[((b)*128 + (rr))*36 + (cc)]
#define PVB(b,rr,cc) dsm[2*128*36 + ((b)*32 + (rr))*136 + (cc)]

__global__ __launch_bounds__(256) void k_pv()
{
    extern __shared__ unsigned dsm[];
    const int t = threadIdx.x;
    const int lane = t & 31, warp = t >> 5;
    const int m0 = (warp >> 2) * 64, n0 = (warp & 3) * 32;
    const int r = lane >> 2, cl = lane & 3;
    const int bh = blockIdx.x, y = blockIdx.y, z = blockIdx.z;
    const int rowbase = bh * 256 + y * 128;

    float ratio[8], inv2[8];
#pragma unroll
    for (int i = 0; i < 8; i++) {
        int lr = m0 + (i >> 1) * 16 + (i & 1) * 8 + r;
        float rs1 = g_rs1[rowbase + lr], rs2 = g_rs2[rowbase + lr];
        ratio[i] = __fdividef(rs2, rs1);
        inv2[i] = __fdividef(1.0f, rs2);
    }

    float acc[4][4][4] = {};

    auto srcA = [&](int ch) -> const float* {
        return (ch < 8 ? g_aH : g_aV) + (size_t)rowbase * 256 + (ch & 7) * 32;
    };
    auto srcB = [&](int ch) -> const float* {
        return (ch < 8 ? g_vH : g_vV) + (size_t)bh * 524288
               + (size_t)((ch & 7) * 32) * 2048 + z * 128;
    };

    // prologue
    {
        const float* A = srcA(0); const float* Bp = srcB(0);
#pragma unroll
        for (int p = 0; p < 4; p++) {
            int lin = t + p * 256, row = lin >> 3, seg = lin & 7;
            cpa16(&PVA(0, row, seg * 4), A + (size_t)row * 256 + seg * 4);
        }
#pragma unroll
        for (int p = 0; p < 4; p++) {
            int lin = t + p * 256, row = lin >> 5, seg = lin & 31;
            cpa16(&PVB(0, row, seg * 4), Bp + (size_t)row * 2048 + seg * 4);
        }
        CP_COMMIT();
    }

    for (int ch = 0; ch < 16; ch++) {
        if (ch < 15) {
            int nb = (ch + 1) & 1;
            const float* A = srcA(ch + 1); const float* Bp = srcB(ch + 1);
#pragma unroll
            for (int p = 0; p < 4; p++) {
                int lin = t + p * 256, row = lin >> 3, seg = lin & 7;
                cpa16(&PVA(nb, row, seg * 4), A + (size_t)row * 256 + seg * 4);
            }
#pragma unroll
            for (int p = 0; p < 4; p++) {
                int lin = t + p * 256, row = lin >> 5, seg = lin & 31;
                cpa16(&PVB(nb, row, seg * 4), Bp + (size_t)row * 2048 + seg * 4);
            }
            CP_COMMIT();
            CP_WAIT1();
        } else {
            CP_WAIT0();
        }
        __syncthreads();
        const int buf = ch & 1;
#pragma unroll
        for (int kk = 0; kk < 32; kk += 8) {
            unsigned af[4][4], bf[4][2];
#pragma unroll
            for (int mt = 0; mt < 4; mt++) {
                int mr = m0 + mt * 16 + r;
                af[mt][0] = PVA(buf, mr, kk+cl);   af[mt][1] = PVA(buf, mr+8, kk+cl);
                af[mt][2] = PVA(buf, mr, kk+cl+4); af[mt][3] = PVA(buf, mr+8, kk+cl+4);
            }
#pragma unroll
            for (int nt = 0; nt < 4; nt++) {
                int nc = n0 + nt * 8 + r;
                bf[nt][0] = PVB(buf, kk+cl, nc); bf[nt][1] = PVB(buf, kk+cl+4, nc);
            }
#pragma unroll
            for (int mt = 0; mt < 4; mt++)
#pragma unroll
                for (int nt = 0; nt < 4; nt++)
                    mma_tf32(acc[mt][nt], af[mt][0], af[mt][1], af[mt][2], af[mt][3],
                             bf[nt][0], bf[nt][1]);
        }
        if (ch == 7) {  // end of H half: acc *= rs2/rs1 (per m-row)
#pragma unroll
            for (int mt = 0; mt < 4; mt++)
#pragma unroll
                for (int rr = 0; rr < 2; rr++) {
                    float f = ratio[mt*2+rr];
#pragma unroll
                    for (int nt = 0; nt < 4; nt++) {
                        acc[mt][nt][rr*2]   *= f;
                        acc[mt][nt][rr*2+1] *= f;
                    }
                }
        }
        __syncthreads();
    }

    const int b = bh >> 3, h = bh & 7;
#pragma unroll
    for (int mt = 0; mt < 4; mt++) {
#pragma unroll
        for (int rr = 0; rr < 2; rr++) {
            int s = y * 128 + m0 + mt * 16 + rr * 8 + r;
            float f = inv2[mt*2+rr];
#pragma unroll
            for (int nt = 0; nt < 4; nt++) {
                int d = z * 128 + n0 + nt * 8 + 2 * cl;
                size_t tok = (size_t)b * 65536 + (size_t)s * 256 + h * 32 + (d >> 6);
                float2 o;
                o.x = acc[mt][nt][rr*2]   * f;
                o.y = acc[mt][nt][rr*2+1] * f;
                *(float2*)(g_x + tok * 64 + (d & 63)) = o;
            }
        }
    }
}

// ---------------------------------------------------------------------------
// Kernel 5: output projection (tf32 MMA)
// ---------------------------------------------------------------------------
__global__ __launch_bounds__(256) void k_proj(const float* __restrict__ Wp,
                                              const float* __restrict__ bp,
                                              float* __restrict__ out)
{
    __shared__ unsigned sA[128][36];
    __shared__ unsigned sB[64][36];
    const int t = threadIdx.x;
    const int lane = t & 31, warp = t >> 5;
    const int m0 = (warp >> 1) * 32, n0 = (warp & 1) * 32;
    const int r = lane >> 2, cl = lane & 3;
    const size_t T0 = (size_t)blockIdx.x * 128;

    float acc[2][4][4] = {};

    for (int k0 = 0; k0 < 64; k0 += 32) {
#pragma unroll
        for (int p = 0; p < 4; p++) {
            int row = (t >> 3) + p * 32, c4 = (t & 7) << 2;
            float4 v = *(const float4*)(g_x + (T0 + row) * 64 + k0 + c4);
            sA[row][c4] = f2tf(v.x); sA[row][c4+1] = f2tf(v.y);
            sA[row][c4+2] = f2tf(v.z); sA[row][c4+3] = f2tf(v.w);
        }
#pragma unroll
        for (int p = 0; p < 2; p++) {
            int row = (t >> 3) + p * 32, c4 = (t & 7) << 2;
            if (row < 64) {
                float4 w4 = *(const float4*)(Wp + (size_t)row * 64 + k0 + c4);
                sB[row][c4] = f2tf(w4.x); sB[row][c4+1] = f2tf(w4.y);
                sB[row][c4+2] = f2tf(w4.z); sB[row][c4+3] = f2tf(w4.w);
            }
        }
        __syncthreads();
#pragma unroll
        for (int kk = 0; kk < 32; kk += 8) {
            unsigned af[2][4], bf[4][2];
#pragma unroll
            for (int mt = 0; mt < 2; mt++) {
                int mr = m0 + mt * 16 + r;
                af[mt][0] = sA[mr][kk+cl];   af[mt][1] = sA[mr+8][kk+cl];
                af[mt][2] = sA[mr][kk+cl+4]; af[mt][3] = sA[mr+8][kk+cl+4];
            }
#pragma unroll
            for (int nt = 0; nt < 4; nt++) {
                int nr = n0 + nt * 8 + r;
                bf[nt][0] = sB[nr][kk+cl]; bf[nt][1] = sB[nr][kk+cl+4];
            }
#pragma unroll
            for (int mt = 0; mt < 2; mt++)
#pragma unroll
                for (int nt = 0; nt < 4; nt++)
                    mma_tf32(acc[mt][nt], af[mt][0], af[mt][1], af[mt][2], af[mt][3],
                             bf[nt][0], bf[nt][1]);
        }
        __syncthreads();
    }

#pragma unroll
    for (int mt = 0; mt < 2; mt++) {
#pragma unroll
        for (int rr = 0; rr < 2; rr++) {
            size_t T = T0 + m0 + mt * 16 + r + rr * 8;
#pragma unroll
            for (int nt = 0; nt < 4; nt++) {
                int col = n0 + nt * 8 + 2 * cl;
                float2 bv = *(const float2*)(bp + col);
                float2 o;
                o.x = acc[mt][nt][rr*2]   + bv.x;
                o.y = acc[mt][nt][rr*2+1] + bv.y;
                *(float2*)(out + T * 64 + col) = o;
            }
        }
    }
}

// ---------------------------------------------------------------------------
extern "C" void kernel_launch(void* const* d_in, const int* in_sizes, int n_in,
                              void* d_out, int out_size)
{
    const float* x      = (const float*)d_in[0];
    const float* qkv_w  = (const float*)d_in[1];
    const float* qkv_b  = (const float*)d_in[2];
    const float* proj_w = (const float*)d_in[3];
    const float* proj_b = (const float*)d_in[4];
    const float* t1     = (const float*)d_in[5];
    const float* t2     = (const float*)d_in[6];
    float* out          = (float*)d_out;

    cudaFuncSetAttribute(k_simsm, cudaFuncAttributeMaxDynamicSharedMemorySize, 208896);
    cudaFuncSetAttribute(k_pv,    cudaFuncAttributeMaxDynamicSharedMemorySize, 71680);

    k_qkv<<<dim3(4096, 2), 256>>>(x, qkv_w, qkv_b);
    k_norm<<<dim3(16384, 2), 256>>>();
    k_simsm<<<dim3(64, 2), 256, 208896>>>(t1, t2);
    k_pv<<<dim3(64, 2, 16), 256, 71680>>>();
    k_proj<<<4096, 256>>>(proj_w, proj_b, out);
}

// round 5
// speedup vs baseline: 3.6485x; 1.0212x over previous
#include <cuda_runtime.h>
#include <math.h>

// B=8, S=256, N=256, C=64, NH=8, D=2048
#define BB 8
#define SS 256

// Scratch (device globals). q/k/vH/vV/aH/aV stored pre-rounded to tf32.
__device__ float g_q [(size_t)BB*8*SS*2048];
__device__ float g_k [(size_t)BB*8*SS*2048];
__device__ float g_vH[(size_t)BB*8*SS*2048];
__device__ float g_vV[(size_t)BB*8*SS*2048];
__device__ float g_inq[BB*8*SS];              // sum of squares (q rows)
__device__ float g_ink[BB*8*SS];              // sum of squares (k rows)
__device__ float g_aH [(size_t)BB*8*SS*SS];   // unnormalized exp
__device__ float g_aV [(size_t)BB*8*SS*SS];
__device__ float g_rs1[BB*8*SS];              // softmax row sums
__device__ float g_rs2[BB*8*SS];

__device__ __forceinline__ unsigned f2tf(float f) {
    unsigned u;
    asm("cvt.rna.tf32.f32 %0, %1;" : "=r"(u) : "f"(f));
    return u;
}

__device__ __forceinline__ void mma_tf32(float* c, unsigned a0, unsigned a1,
                                         unsigned a2, unsigned a3,
                                         unsigned b0, unsigned b1) {
    asm volatile(
        "mma.sync.aligned.m16n8k8.row.col.f32.tf32.tf32.f32 "
        "{%0,%1,%2,%3}, {%4,%5,%6,%7}, {%8,%9}, {%0,%1,%2,%3};"
        : "+f"(c[0]), "+f"(c[1]), "+f"(c[2]), "+f"(c[3])
        : "r"(a0), "r"(a1), "r"(a2), "r"(a3), "r"(b0), "r"(b1));
}

__device__ __forceinline__ void cpa16(void* s, const void* g) {
    unsigned sa = (unsigned)__cvta_generic_to_shared(s);
    asm volatile("cp.async.cg.shared.global [%0], [%1], 16;" :: "r"(sa), "l"(g));
}
#define CP_COMMIT() asm volatile("cp.async.commit_group;")
#define CP_WAIT1()  asm volatile("cp.async.wait_group 1;")
#define CP_WAIT0()  asm volatile("cp.async.wait_group 0;")

// ---------------------------------------------------------------------------
// Kernel 0: zero the sumsq accumulators
// ---------------------------------------------------------------------------
__global__ void k_zero()
{
    int i = blockIdx.x * 1024 + threadIdx.x;
    if (i < 16384) { g_inq[i] = 0.0f; g_ink[i] = 0.0f; }
}

// ---------------------------------------------------------------------------
// Kernel 1: QKV GEMM (tf32 MMA), scatter + tf32-round at write,
// fused q/k row sum-of-squares via shuffle-reduce + atomicAdd.
// ---------------------------------------------------------------------------
__global__ __launch_bounds__(256) void k_qkv(const float* __restrict__ X,
                                             const float* __restrict__ W,
                                             const float* __restrict__ bias)
{
    __shared__ unsigned sA[128][36];
    __shared__ unsigned sB[128][36];
    const int t = threadIdx.x;
    const int lane = t & 31, warp = t >> 5;
    const int m0 = (warp >> 2) * 64, n0 = (warp & 3) * 32;
    const int r = lane >> 2, cl = lane & 3;
    const size_t T0 = (size_t)blockIdx.x * 128;
    const int f0 = blockIdx.y * 128;

    float acc[4][4][4] = {};

    for (int k0 = 0; k0 < 64; k0 += 32) {
#pragma unroll
        for (int p = 0; p < 4; p++) {
            int row = (t >> 3) + p * 32, c4 = (t & 7) << 2;
            float4 v = *(const float4*)(X + (T0 + row) * 64 + k0 + c4);
            sA[row][c4] = f2tf(v.x); sA[row][c4+1] = f2tf(v.y);
            sA[row][c4+2] = f2tf(v.z); sA[row][c4+3] = f2tf(v.w);
            float4 w4 = *(const float4*)(W + (size_t)(f0 + row) * 64 + k0 + c4);
            sB[row][c4] = f2tf(w4.x); sB[row][c4+1] = f2tf(w4.y);
            sB[row][c4+2] = f2tf(w4.z); sB[row][c4+3] = f2tf(w4.w);
        }
        __syncthreads();
#pragma unroll
        for (int kk = 0; kk < 32; kk += 8) {
            unsigned af[4][4], bf[4][2];
#pragma unroll
            for (int mt = 0; mt < 4; mt++) {
                int mr = m0 + mt * 16 + r;
                af[mt][0] = sA[mr][kk+cl];     af[mt][1] = sA[mr+8][kk+cl];
                af[mt][2] = sA[mr][kk+cl+4];   af[mt][3] = sA[mr+8][kk+cl+4];
            }
#pragma unroll
            for (int nt = 0; nt < 4; nt++) {
                int nr = n0 + nt * 8 + r;
                bf[nt][0] = sB[nr][kk+cl]; bf[nt][1] = sB[nr][kk+cl+4];
            }
#pragma unroll
            for (int mt = 0; mt < 4; mt++)
#pragma unroll
                for (int nt = 0; nt < 4; nt++)
                    mma_tf32(acc[mt][nt], af[mt][0], af[mt][1], af[mt][2], af[mt][3],
                             bf[nt][0], bf[nt][1]);
        }
        __syncthreads();
    }

#pragma unroll
    for (int mt = 0; mt < 4; mt++) {
#pragma unroll
        for (int rr = 0; rr < 2; rr++) {
            size_t T = T0 + m0 + mt * 16 + r + rr * 8;
            int b = (int)(T >> 16);
            int s = (int)((T >> 8) & 255);
            int n = (int)(T & 255);
            int g = n >> 6;
            int h = (n >> 3) & 7;
            float ssq = 0.0f;
#pragma unroll
            for (int nt = 0; nt < 4; nt++) {
                int f = f0 + n0 + nt * 8 + 2 * cl;
                float2 bv = *(const float2*)(bias + f);
                float a0 = acc[mt][nt][rr*2]   + bv.x;
                float a1 = acc[mt][nt][rr*2+1] + bv.y;
                ssq += a0 * a0 + a1 * a1;
                float2 val;
                val.x = __uint_as_float(f2tf(a0));
                val.y = __uint_as_float(f2tf(a1));
                int d0 = ((n & 7) << 8) + f;
                float* dst; size_t idx;
                if (g == 3) {
                    int h2 = s >> 5;
                    int s2 = h * 32 + (d0 >> 6);
                    int d2 = ((s & 31) << 6) + (d0 & 63);
                    dst = g_vV;
                    idx = (((size_t)(b * 8 + h2) * 256 + s2) << 11) + d2;
                } else {
                    dst = (g == 0) ? g_q : (g == 1 ? g_k : g_vH);
                    idx = (((size_t)(b * 8 + h) * 256 + s) << 11) + d0;
                }
                *(float2*)(dst + idx) = val;
            }
            if (g < 2) {
                ssq += __shfl_xor_sync(0xffffffffu, ssq, 1);
                ssq += __shfl_xor_sync(0xffffffffu, ssq, 2);
                if (cl == 0)
                    atomicAdd((g == 0 ? g_inq : g_ink) + (b * 8 + h) * 256 + s, ssq);
            }
        }
    }
}

// ---------------------------------------------------------------------------
// Kernel 2: fused sim + dual softmax. Tile 128x256 (full rows), grid (64,2).
// Reads sumsq from g_inq/g_ink, computes inverse norms on the fly.
// ---------------------------------------------------------------------------
#define SIMQ(b,rr,cc) dsm[((b)*128 + (rr))*68 + (cc)]
#define SIMK(b,rr,cc) dsm[2*128*68 + ((b)*256 + (rr))*68 + (cc)]

__global__ __launch_bounds__(256, 1) void k_simsm(const float* __restrict__ t1p,
                                                  const float* __restrict__ t2p)
{
    extern __shared__ unsigned dsm[];
    const int t = threadIdx.x;
    const int lane = t & 31, warp = t >> 5;
    const int m0 = (warp >> 2) * 64;
    const int nwarp = warp & 3;
    const int n0 = nwarp * 64;
    const int r = lane >> 2, cl = lane & 3;
    const int bh = blockIdx.x, y = blockIdx.y;
    const float* Qb = g_q + ((size_t)bh * 256 + y * 128) * 2048;
    const float* Kb = g_k + (size_t)bh * 256 * 2048;

    float acc[4][8][4] = {};

    {
#pragma unroll
        for (int p = 0; p < 8; p++) {
            int lin = t + p * 256, row = lin >> 4, seg = lin & 15;
            cpa16(&SIMQ(0, row, seg * 4), Qb + (size_t)row * 2048 + seg * 4);
        }
#pragma unroll
        for (int p = 0; p < 16; p++) {
            int lin = t + p * 256, row = lin >> 4, seg = lin & 15;
            cpa16(&SIMK(0, row, seg * 4), Kb + (size_t)row * 2048 + seg * 4);
        }
        CP_COMMIT();
    }

    for (int ch = 0; ch < 32; ch++) {
        if (ch < 31) {
            int nb = (ch + 1) & 1, k0 = (ch + 1) * 64;
#pragma unroll
            for (int p = 0; p < 8; p++) {
                int lin = t + p * 256, row = lin >> 4, seg = lin & 15;
                cpa16(&SIMQ(nb, row, seg * 4), Qb + (size_t)row * 2048 + k0 + seg * 4);
            }
#pragma unroll
            for (int p = 0; p < 16; p++) {
                int lin = t + p * 256, row = lin >> 4, seg = lin & 15;
                cpa16(&SIMK(nb, row, seg * 4), Kb + (size_t)row * 2048 + k0 + seg * 4);
            }
            CP_COMMIT();
            CP_WAIT1();
        } else {
            CP_WAIT0();
        }
        __syncthreads();
        const int buf = ch & 1;
#pragma unroll
        for (int kk = 0; kk < 64; kk += 8) {
            unsigned af[4][4], bf[8][2];
#pragma unroll
            for (int mt = 0; mt < 4; mt++) {
                int mr = m0 + mt * 16 + r;
                af[mt][0] = SIMQ(buf, mr, kk+cl);   af[mt][1] = SIMQ(buf, mr+8, kk+cl);
                af[mt][2] = SIMQ(buf, mr, kk+cl+4); af[mt][3] = SIMQ(buf, mr+8, kk+cl+4);
            }
#pragma unroll
            for (int nt = 0; nt < 8; nt++) {
                int nr = n0 + nt * 8 + r;
                bf[nt][0] = SIMK(buf, nr, kk+cl); bf[nt][1] = SIMK(buf, nr, kk+cl+4);
            }
#pragma unroll
            for (int mt = 0; mt < 4; mt++)
#pragma unroll
                for (int nt = 0; nt < 8; nt++)
                    mma_tf32(acc[mt][nt], af[mt][0], af[mt][1], af[mt][2], af[mt][3],
                             bf[nt][0], bf[nt][1]);
        }
        __syncthreads();
    }

    // ---------------- epilogue: scale + dual softmax ----------------
    const int h = bh & 7;
    const float T1 = t1p[h], T2 = t2p[h];
    const int rowbase = bh * 256 + y * 128;

    float iq[8];
#pragma unroll
    for (int i = 0; i < 8; i++) {
        float ssq = g_inq[rowbase + m0 + (i >> 1) * 16 + (i & 1) * 8 + r];
        iq[i] = 1.0f / fmaxf(sqrtf(ssq), 1e-12f);
    }
    float ikv[8][2];
#pragma unroll
    for (int nt = 0; nt < 8; nt++) {
        float2 v2 = *(const float2*)(g_ink + bh * 256 + n0 + nt * 8 + 2 * cl);
        ikv[nt][0] = 1.0f / fmaxf(sqrtf(v2.x), 1e-12f);
        ikv[nt][1] = 1.0f / fmaxf(sqrtf(v2.y), 1e-12f);
    }
#pragma unroll
    for (int mt = 0; mt < 4; mt++)
#pragma unroll
        for (int nt = 0; nt < 8; nt++)
#pragma unroll
            for (int rr = 0; rr < 2; rr++) {
                acc[mt][nt][rr*2]   *= iq[mt*2+rr] * ikv[nt][0];
                acc[mt][nt][rr*2+1] *= iq[mt*2+rr] * ikv[nt][1];
            }

    float mx[8], mn[8];
#pragma unroll
    for (int i = 0; i < 8; i++) { mx[i] = -3.0e38f; mn[i] = 3.0e38f; }
#pragma unroll
    for (int mt = 0; mt < 4; mt++)
#pragma unroll
        for (int rr = 0; rr < 2; rr++) {
            int i = mt * 2 + rr;
#pragma unroll
            for (int nt = 0; nt < 8; nt++) {
                mx[i] = fmaxf(mx[i], fmaxf(acc[mt][nt][rr*2], acc[mt][nt][rr*2+1]));
                mn[i] = fminf(mn[i], fminf(acc[mt][nt][rr*2], acc[mt][nt][rr*2+1]));
            }
        }
#pragma unroll
    for (int o = 1; o <= 2; o <<= 1)
#pragma unroll
        for (int i = 0; i < 8; i++) {
            mx[i] = fmaxf(mx[i], __shfl_xor_sync(0xffffffffu, mx[i], o));
            mn[i] = fminf(mn[i], __shfl_xor_sync(0xffffffffu, mn[i], o));
        }

    float* sMx = (float*)dsm;
    float* sMn = (float*)dsm + 512;
    if (cl == 0) {
#pragma unroll
        for (int i = 0; i < 8; i++) {
            int lr = m0 + (i >> 1) * 16 + (i & 1) * 8 + r;
            sMx[lr * 4 + nwarp] = mx[i];
            sMn[lr * 4 + nwarp] = mn[i];
        }
    }
    __syncthreads();
    float M1[8], M2[8];
#pragma unroll
    for (int i = 0; i < 8; i++) {
        int lr = m0 + (i >> 1) * 16 + (i & 1) * 8 + r;
        float vmx = sMx[lr*4], vmn = sMn[lr*4];
#pragma unroll
        for (int k = 1; k < 4; k++) {
            vmx = fmaxf(vmx, sMx[lr*4+k]);
            vmn = fminf(vmn, sMn[lr*4+k]);
        }
        M1[i] = (T1 >= 0.0f) ? T1 * vmx : T1 * vmn;
        M2[i] = (T2 >= 0.0f) ? T2 * vmx : T2 * vmn;
    }

    float s1[8] = {}, s2[8] = {};
#pragma unroll
    for (int mt = 0; mt < 4; mt++)
#pragma unroll
        for (int rr = 0; rr < 2; rr++) {
            int i = mt * 2 + rr;
            int lr = m0 + mt * 16 + rr * 8 + r;
            size_t rowoff = (size_t)(rowbase + lr) * 256;
#pragma unroll
            for (int nt = 0; nt < 8; nt++) {
                int col = n0 + nt * 8 + 2 * cl;
                float v0 = acc[mt][nt][rr*2], v1 = acc[mt][nt][rr*2+1];
                float e10 = __expf(v0 * T1 - M1[i]);
                float e11 = __expf(v1 * T1 - M1[i]);
                float e20 = __expf(v0 * T2 - M2[i]);
                float e21 = __expf(v1 * T2 - M2[i]);
                s1[i] += e10 + e11;
                s2[i] += e20 + e21;
                float2 o1, o2;
                o1.x = __uint_as_float(f2tf(e10)); o1.y = __uint_as_float(f2tf(e11));
                o2.x = __uint_as_float(f2tf(e20)); o2.y = __uint_as_float(f2tf(e21));
                *(float2*)(g_aH + rowoff + col) = o1;
                *(float2*)(g_aV + rowoff + col) = o2;
            }
        }
#pragma unroll
    for (int o = 1; o <= 2; o <<= 1)
#pragma unroll
        for (int i = 0; i < 8; i++) {
            s1[i] += __shfl_xor_sync(0xffffffffu, s1[i], o);
            s2[i] += __shfl_xor_sync(0xffffffffu, s2[i], o);
        }
    __syncthreads();
    float* sS1 = (float*)dsm;
    float* sS2 = (float*)dsm + 512;
    if (cl == 0) {
#pragma unroll
        for (int i = 0; i < 8; i++) {
            int lr = m0 + (i >> 1) * 16 + (i & 1) * 8 + r;
            sS1[lr * 4 + nwarp] = s1[i];
            sS2[lr * 4 + nwarp] = s2[i];
        }
    }
    __syncthreads();
    if (nwarp == 0 && cl == 0) {
#pragma unroll
        for (int i = 0; i < 8; i++) {
            int lr = m0 + (i >> 1) * 16 + (i & 1) * 8 + r;
            float tt1 = sS1[lr*4] + sS1[lr*4+1] + sS1[lr*4+2] + sS1[lr*4+3];
            float tt2 = sS2[lr*4] + sS2[lr*4+1] + sS2[lr*4+2] + sS2[lr*4+3];
            g_rs1[rowbase + lr] = tt1;
            g_rs2[rowbase + lr] = tt2;
        }
    }
}

// ---------------------------------------------------------------------------
// Kernel 3: x = (E1 @ vH)/rs1 + (E2 @ vV)/rs2, then FUSED output projection:
// out = x @ proj_w^T + proj_b, written directly to d_out.
// Each block's 128x128 tile == 256 complete 64-dim token rows.
// grid (64, 2, 16). Dyn smem 87040 B.
// ---------------------------------------------------------------------------
#define PVA(b,rr,cc) dsm[((b)*128 + (rr))*36 + (cc)]
#define PVB(b,rr,cc) dsm[2*128*36 + ((b)*32 + (rr))*136 + (cc)]
#define TOK(rr,cc)   dsm[(rr)*68 + (cc)]
#define WPS(rr,cc)   dsm[17408 + (rr)*68 + (cc)]

__global__ __launch_bounds__(256) void k_pv(const float* __restrict__ Wp,
                                            const float* __restrict__ bp,
                                            float* __restrict__ out)
{
    extern __shared__ unsigned dsm[];
    const int t = threadIdx.x;
    const int lane = t & 31, warp = t >> 5;
    const int m0 = (warp >> 2) * 64, n0 = (warp & 3) * 32;
    const int r = lane >> 2, cl = lane & 3;
    const int bh = blockIdx.x, y = blockIdx.y, z = blockIdx.z;
    const int rowbase = bh * 256 + y * 128;

    float ratio[8], inv2[8];
#pragma unroll
    for (int i = 0; i < 8; i++) {
        int lr = m0 + (i >> 1) * 16 + (i & 1) * 8 + r;
        float rs1 = g_rs1[rowbase + lr], rs2 = g_rs2[rowbase + lr];
        ratio[i] = __fdividef(rs2, rs1);
        inv2[i] = __fdividef(1.0f, rs2);
    }

    float acc[4][4][4] = {};

    auto srcA = [&](int ch) -> const float* {
        return (ch < 8 ? g_aH : g_aV) + (size_t)rowbase * 256 + (ch & 7) * 32;
    };
    auto srcB = [&](int ch) -> const float* {
        return (ch < 8 ? g_vH : g_vV) + (size_t)bh * 524288
               + (size_t)((ch & 7) * 32) * 2048 + z * 128;
    };

    {
        const float* A = srcA(0); const float* Bp2 = srcB(0);
#pragma unroll
        for (int p = 0; p < 4; p++) {
            int lin = t + p * 256, row = lin >> 3, seg = lin & 7;
            cpa16(&PVA(0, row, seg * 4), A + (size_t)row * 256 + seg * 4);
        }
#pragma unroll
        for (int p = 0; p < 4; p++) {
            int lin = t + p * 256, row = lin >> 5, seg = lin & 31;
            cpa16(&PVB(0, row, seg * 4), Bp2 + (size_t)row * 2048 + seg * 4);
        }
        CP_COMMIT();
    }

    for (int ch = 0; ch < 16; ch++) {
        if (ch < 15) {
            int nb = (ch + 1) & 1;
            const float* A = srcA(ch + 1); const float* Bp2 = srcB(ch + 1);
#pragma unroll
            for (int p = 0; p < 4; p++) {
                int lin = t + p * 256, row = lin >> 3, seg = lin & 7;
                cpa16(&PVA(nb, row, seg * 4), A + (size_t)row * 256 + seg * 4);
            }
#pragma unroll
            for (int p = 0; p < 4; p++) {
                int lin = t + p * 256, row = lin >> 5, seg = lin & 31;
                cpa16(&PVB(nb, row, seg * 4), Bp2 + (size_t)row * 2048 + seg * 4);
            }
            CP_COMMIT();
            CP_WAIT1();
        } else {
            CP_WAIT0();
        }
        __syncthreads();
        const int buf = ch & 1;
#pragma unroll
        for (int kk = 0; kk < 32; kk += 8) {
            unsigned af[4][4], bf[4][2];
#pragma unroll
            for (int mt = 0; mt < 4; mt++) {
                int mr = m0 + mt * 16 + r;
                af[mt][0] = PVA(buf, mr, kk+cl);   af[mt][1] = PVA(buf, mr+8, kk+cl);
                af[mt][2] = PVA(buf, mr, kk+cl+4); af[mt][3] = PVA(buf, mr+8, kk+cl+4);
            }
#pragma unroll
            for (int nt = 0; nt < 4; nt++) {
                int nc = n0 + nt * 8 + r;
                bf[nt][0] = PVB(buf, kk+cl, nc); bf[nt][1] = PVB(buf, kk+cl+4, nc);
            }
#pragma unroll
            for (int mt = 0; mt < 4; mt++)
#pragma unroll
                for (int nt = 0; nt < 4; nt++)
                    mma_tf32(acc[mt][nt], af[mt][0], af[mt][1], af[mt][2], af[mt][3],
                             bf[nt][0], bf[nt][1]);
        }
        if (ch == 7) {
#pragma unroll
            for (int mt = 0; mt < 4; mt++)
#pragma unroll
                for (int rr = 0; rr < 2; rr++) {
                    float f = ratio[mt*2+rr];
#pragma unroll
                    for (int nt = 0; nt < 4; nt++) {
                        acc[mt][nt][rr*2]   *= f;
                        acc[mt][nt][rr*2+1] *= f;
                    }
                }
        }
        __syncthreads();
    }

    // -------- stage normalized x rows as 256 complete tokens + load Wp ------
    __syncthreads();
    // half: d>>6 within this block's 128-wide d tile is fixed per n-warp
    const int half = (n0 >= 64) ? 1 : 0;
#pragma unroll
    for (int mt = 0; mt < 4; mt++) {
#pragma unroll
        for (int rr = 0; rr < 2; rr++) {
            int s_local = m0 + mt * 16 + rr * 8 + r;
            float f = inv2[mt*2+rr];
            int tt = s_local * 2 + half;
#pragma unroll
            for (int nt = 0; nt < 4; nt++) {
                int c = ((n0 & 63) + nt * 8 + 2 * cl);
                unsigned u0 = f2tf(acc[mt][nt][rr*2]   * f);
                unsigned u1 = f2tf(acc[mt][nt][rr*2+1] * f);
                TOK(tt, c)   = u0;
                TOK(tt, c+1) = u1;
            }
        }
    }
    // Wp: 64x64, row-major (c, k) -> smem [c][k]
    for (int i = t; i < 1024; i += 256) {
        int row = i >> 4, c4 = (i & 15) << 2;
        float4 w4 = *(const float4*)(Wp + (size_t)row * 64 + c4);
        WPS(row, c4) = f2tf(w4.x); WPS(row, c4+1) = f2tf(w4.y);
        WPS(row, c4+2) = f2tf(w4.z); WPS(row, c4+3) = f2tf(w4.w);
    }
    __syncthreads();

    // -------- fused projection: each warp projects 32 token rows ------------
    float acc2[2][8][4] = {};
    const int tt0 = warp * 32;
#pragma unroll
    for (int kk = 0; kk < 64; kk += 8) {
        unsigned af[2][4], bf[8][2];
#pragma unroll
        for (int mt = 0; mt < 2; mt++) {
            int mr = tt0 + mt * 16 + r;
            af[mt][0] = TOK(mr, kk+cl);   af[mt][1] = TOK(mr+8, kk+cl);
            af[mt][2] = TOK(mr, kk+cl+4); af[mt][3] = TOK(mr+8, kk+cl+4);
        }
#pragma unroll
        for (int nt = 0; nt < 8; nt++) {
            int nr = nt * 8 + r;
            bf[nt][0] = WPS(nr, kk+cl); bf[nt][1] = WPS(nr, kk+cl+4);
        }
#pragma unroll
        for (int mt = 0; mt < 2; mt++)
#pragma unroll
            for (int nt = 0; nt < 8; nt++)
                mma_tf32(acc2[mt][nt], af[mt][0], af[mt][1], af[mt][2], af[mt][3],
                         bf[nt][0], bf[nt][1]);
    }

    const int b = bh >> 3, h = bh & 7;
#pragma unroll
    for (int mt = 0; mt < 2; mt++) {
#pragma unroll
        for (int rr = 0; rr < 2; rr++) {
            int tt = tt0 + mt * 16 + rr * 8 + r;
            int s = y * 128 + (tt >> 1);
            int nn = h * 32 + 2 * z + (tt & 1);
            size_t rowoff = ((size_t)b * 65536 + (size_t)s * 256 + nn) * 64;
#pragma unroll
            for (int nt = 0; nt < 8; nt++) {
                int c = nt * 8 + 2 * cl;
                float2 bv = *(const float2*)(bp + c);
                float2 o;
                o.x = acc2[mt][nt][rr*2]   + bv.x;
                o.y = acc2[mt][nt][rr*2+1] + bv.y;
                *(float2*)(out + rowoff + c) = o;
            }
        }
    }
}

// ---------------------------------------------------------------------------
extern "C" void kernel_launch(void* const* d_in, const int* in_sizes, int n_in,
                              void* d_out, int out_size)
{
    const float* x      = (const float*)d_in[0];
    const float* qkv_w  = (const float*)d_in[1];
    const float* qkv_b  = (const float*)d_in[2];
    const float* proj_w = (const float*)d_in[3];
    const float* proj_b = (const float*)d_in[4];
    const float* t1     = (const float*)d_in[5];
    const float* t2     = (const float*)d_in[6];
    float* out          = (float*)d_out;

    cudaFuncSetAttribute(k_simsm, cudaFuncAttributeMaxDynamicSharedMemorySize, 208896);
    cudaFuncSetAttribute(k_pv,    cudaFuncAttributeMaxDynamicSharedMemorySize, 87040);

    k_zero<<<16, 1024>>>();
    k_qkv<<<dim3(4096, 2), 256>>>(x, qkv_w, qkv_b);
    k_simsm<<<dim3(64, 2), 256, 208896>>>(t1, t2);
    k_pv<<<dim3(64, 2, 16), 256, 87040>>>(proj_w, proj_b, out);
}

// round 8
// speedup vs baseline: 4.1036x; 1.1247x over previous
#include <cuda_runtime.h>
#include <math.h>

// B=8, S=256, N=256, C=64, NH=8, D=2048
#define BB 8
#define SS 256

// Scratch (device globals). q/k/vH/vV/aH/aV stored pre-rounded to tf32.
__device__ float g_q [(size_t)BB*8*SS*2048];
__device__ float g_k [(size_t)BB*8*SS*2048];
__device__ float g_vH[(size_t)BB*8*SS*2048];
__device__ float g_vV[(size_t)BB*8*SS*2048];
__device__ float g_inq[BB*8*SS];              // sum of squares (q rows)
__device__ float g_ink[BB*8*SS];              // sum of squares (k rows)
__device__ float g_aH [(size_t)BB*8*SS*SS];   // unnormalized exp
__device__ float g_aV [(size_t)BB*8*SS*SS];
__device__ float g_rs1[BB*8*SS];              // softmax row sums
__device__ float g_rs2[BB*8*SS];

__device__ __forceinline__ unsigned f2tf(float f) {
    unsigned u;
    asm("cvt.rna.tf32.f32 %0, %1;" : "=r"(u) : "f"(f));
    return u;
}

__device__ __forceinline__ void mma_tf32(float* c, unsigned a0, unsigned a1,
                                         unsigned a2, unsigned a3,
                                         unsigned b0, unsigned b1) {
    asm volatile(
        "mma.sync.aligned.m16n8k8.row.col.f32.tf32.tf32.f32 "
        "{%0,%1,%2,%3}, {%4,%5,%6,%7}, {%8,%9}, {%0,%1,%2,%3};"
        : "+f"(c[0]), "+f"(c[1]), "+f"(c[2]), "+f"(c[3])
        : "r"(a0), "r"(a1), "r"(a2), "r"(a3), "r"(b0), "r"(b1));
}

__device__ __forceinline__ void cpa16(void* s, const void* g) {
    unsigned sa = (unsigned)__cvta_generic_to_shared(s);
    asm volatile("cp.async.cg.shared.global [%0], [%1], 16;" :: "r"(sa), "l"(g));
}
#define CP_COMMIT() asm volatile("cp.async.commit_group;")
#define CP_WAIT1()  asm volatile("cp.async.wait_group 1;")
#define CP_WAIT0()  asm volatile("cp.async.wait_group 0;")

// ---------------------------------------------------------------------------
// Kernel 0: zero the sumsq accumulators
// ---------------------------------------------------------------------------
__global__ void k_zero()
{
    int i = blockIdx.x * 1024 + threadIdx.x;
    if (i < 16384) { g_inq[i] = 0.0f; g_ink[i] = 0.0f; }
}

// ---------------------------------------------------------------------------
// Kernel 1: QKV GEMM (tf32 MMA), scatter + tf32-round at write,
// fused q/k row sum-of-squares via shuffle-reduce + atomicAdd.
// ---------------------------------------------------------------------------
__global__ __launch_bounds__(256, 2) void k_qkv(const float* __restrict__ X,
                                                const float* __restrict__ W,
                                                const float* __restrict__ bias)
{
    __shared__ unsigned sA[128][36];
    __shared__ unsigned sB[128][36];
    const int t = threadIdx.x;
    const int lane = t & 31, warp = t >> 5;
    const int m0 = (warp >> 2) * 64, n0 = (warp & 3) * 32;
    const int r = lane >> 2, cl = lane & 3;
    const size_t T0 = (size_t)blockIdx.x * 128;
    const int f0 = blockIdx.y * 128;

    float acc[4][4][4] = {};

    for (int k0 = 0; k0 < 64; k0 += 32) {
#pragma unroll
        for (int p = 0; p < 4; p++) {
            int row = (t >> 3) + p * 32, c4 = (t & 7) << 2;
            float4 v = *(const float4*)(X + (T0 + row) * 64 + k0 + c4);
            sA[row][c4] = f2tf(v.x); sA[row][c4+1] = f2tf(v.y);
            sA[row][c4+2] = f2tf(v.z); sA[row][c4+3] = f2tf(v.w);
            float4 w4 = *(const float4*)(W + (size_t)(f0 + row) * 64 + k0 + c4);
            sB[row][c4] = f2tf(w4.x); sB[row][c4+1] = f2tf(w4.y);
            sB[row][c4+2] = f2tf(w4.z); sB[row][c4+3] = f2tf(w4.w);
        }
        __syncthreads();
#pragma unroll
        for (int kk = 0; kk < 32; kk += 8) {
            unsigned af[4][4], bf[4][2];
#pragma unroll
            for (int mt = 0; mt < 4; mt++) {
                int mr = m0 + mt * 16 + r;
                af[mt][0] = sA[mr][kk+cl];     af[mt][1] = sA[mr+8][kk+cl];
                af[mt][2] = sA[mr][kk+cl+4];   af[mt][3] = sA[mr+8][kk+cl+4];
            }
#pragma unroll
            for (int nt = 0; nt < 4; nt++) {
                int nr = n0 + nt * 8 + r;
                bf[nt][0] = sB[nr][kk+cl]; bf[nt][1] = sB[nr][kk+cl+4];
            }
#pragma unroll
            for (int mt = 0; mt < 4; mt++)
#pragma unroll
                for (int nt = 0; nt < 4; nt++)
                    mma_tf32(acc[mt][nt], af[mt][0], af[mt][1], af[mt][2], af[mt][3],
                             bf[nt][0], bf[nt][1]);
        }
        __syncthreads();
    }

#pragma unroll
    for (int mt = 0; mt < 4; mt++) {
#pragma unroll
        for (int rr = 0; rr < 2; rr++) {
            size_t T = T0 + m0 + mt * 16 + r + rr * 8;
            int b = (int)(T >> 16);
            int s = (int)((T >> 8) & 255);
            int n = (int)(T & 255);
            int g = n >> 6;
            int h = (n >> 3) & 7;
            float ssq = 0.0f;
#pragma unroll
            for (int nt = 0; nt < 4; nt++) {
                int f = f0 + n0 + nt * 8 + 2 * cl;
                float2 bv = *(const float2*)(bias + f);
                float a0 = acc[mt][nt][rr*2]   + bv.x;
                float a1 = acc[mt][nt][rr*2+1] + bv.y;
                ssq += a0 * a0 + a1 * a1;
                float2 val;
                val.x = __uint_as_float(f2tf(a0));
                val.y = __uint_as_float(f2tf(a1));
                int d0 = ((n & 7) << 8) + f;
                float* dst; size_t idx;
                if (g == 3) {
                    int h2 = s >> 5;
                    int s2 = h * 32 + (d0 >> 6);
                    int d2 = ((s & 31) << 6) + (d0 & 63);
                    dst = g_vV;
                    idx = (((size_t)(b * 8 + h2) * 256 + s2) << 11) + d2;
                } else {
                    dst = (g == 0) ? g_q : (g == 1 ? g_k : g_vH);
                    idx = (((size_t)(b * 8 + h) * 256 + s) << 11) + d0;
                }
                *(float2*)(dst + idx) = val;
            }
            if (g < 2) {
                ssq += __shfl_xor_sync(0xffffffffu, ssq, 1);
                ssq += __shfl_xor_sync(0xffffffffu, ssq, 2);
                if (cl == 0)
                    atomicAdd((g == 0 ? g_inq : g_ink) + (b * 8 + h) * 256 + s, ssq);
            }
        }
    }
}

// ---------------------------------------------------------------------------
// Kernel 2: fused sim + dual softmax. Tile 128x256 (full rows), grid (64,2).
// 512 threads (16 warps, warp tile 32x64). kc=64 double-buffered cp.async.
// ---------------------------------------------------------------------------
#define SIMQ(b,rr,cc) dsm[((b)*128 + (rr))*68 + (cc)]
#define SIMK(b,rr,cc) dsm[2*128*68 + ((b)*256 + (rr))*68 + (cc)]

__global__ __launch_bounds__(512, 1) void k_simsm(const float* __restrict__ t1p,
                                                  const float* __restrict__ t2p)
{
    extern __shared__ unsigned dsm[];
    const int t = threadIdx.x;
    const int lane = t & 31, warp = t >> 5;
    const int m0 = (warp >> 2) * 32;        // 4 m-warps, 32 rows each
    const int nwarp = warp & 3;
    const int n0 = nwarp * 64;              // 4 n-warps, 64 cols each
    const int r = lane >> 2, cl = lane & 3;
    const int bh = blockIdx.x, y = blockIdx.y;
    const float* Qb = g_q + ((size_t)bh * 256 + y * 128) * 2048;
    const float* Kb = g_k + (size_t)bh * 256 * 2048;

    float acc[2][8][4] = {};

    {
#pragma unroll
        for (int p = 0; p < 4; p++) {
            int lin = t + p * 512, row = lin >> 4, seg = lin & 15;
            cpa16(&SIMQ(0, row, seg * 4), Qb + (size_t)row * 2048 + seg * 4);
        }
#pragma unroll
        for (int p = 0; p < 8; p++) {
            int lin = t + p * 512, row = lin >> 4, seg = lin & 15;
            cpa16(&SIMK(0, row, seg * 4), Kb + (size_t)row * 2048 + seg * 4);
        }
        CP_COMMIT();
    }

    for (int ch = 0; ch < 32; ch++) {
        if (ch < 31) {
            int nb = (ch + 1) & 1, k0 = (ch + 1) * 64;
#pragma unroll
            for (int p = 0; p < 4; p++) {
                int lin = t + p * 512, row = lin >> 4, seg = lin & 15;
                cpa16(&SIMQ(nb, row, seg * 4), Qb + (size_t)row * 2048 + k0 + seg * 4);
            }
#pragma unroll
            for (int p = 0; p < 8; p++) {
                int lin = t + p * 512, row = lin >> 4, seg = lin & 15;
                cpa16(&SIMK(nb, row, seg * 4), Kb + (size_t)row * 2048 + k0 + seg * 4);
            }
            CP_COMMIT();
            CP_WAIT1();
        } else {
            CP_WAIT0();
        }
        __syncthreads();
        const int buf = ch & 1;
#pragma unroll
        for (int kk = 0; kk < 64; kk += 8) {
            unsigned af[2][4], bf[8][2];
#pragma unroll
            for (int mt = 0; mt < 2; mt++) {
                int mr = m0 + mt * 16 + r;
                af[mt][0] = SIMQ(buf, mr, kk+cl);   af[mt][1] = SIMQ(buf, mr+8, kk+cl);
                af[mt][2] = SIMQ(buf, mr, kk+cl+4); af[mt][3] = SIMQ(buf, mr+8, kk+cl+4);
            }
#pragma unroll
            for (int nt = 0; nt < 8; nt++) {
                int nr = n0 + nt * 8 + r;
                bf[nt][0] = SIMK(buf, nr, kk+cl); bf[nt][1] = SIMK(buf, nr, kk+cl+4);
            }
#pragma unroll
            for (int mt = 0; mt < 2; mt++)
#pragma unroll
                for (int nt = 0; nt < 8; nt++)
                    mma_tf32(acc[mt][nt], af[mt][0], af[mt][1], af[mt][2], af[mt][3],
                             bf[nt][0], bf[nt][1]);
        }
        __syncthreads();
    }

    // ---------------- epilogue: scale + dual softmax ----------------
    const int h = bh & 7;
    const float T1 = t1p[h], T2 = t2p[h];
    const int rowbase = bh * 256 + y * 128;

    float iq[4];
#pragma unroll
    for (int i = 0; i < 4; i++) {
        float ssq = g_inq[rowbase + m0 + (i >> 1) * 16 + (i & 1) * 8 + r];
        iq[i] = 1.0f / fmaxf(sqrtf(ssq), 1e-12f);
    }
    float ikv[8][2];
#pragma unroll
    for (int nt = 0; nt < 8; nt++) {
        float2 v2 = *(const float2*)(g_ink + bh * 256 + n0 + nt * 8 + 2 * cl);
        ikv[nt][0] = 1.0f / fmaxf(sqrtf(v2.x), 1e-12f);
        ikv[nt][1] = 1.0f / fmaxf(sqrtf(v2.y), 1e-12f);
    }
#pragma unroll
    for (int mt = 0; mt < 2; mt++)
#pragma unroll
        for (int nt = 0; nt < 8; nt++)
#pragma unroll
            for (int rr = 0; rr < 2; rr++) {
                acc[mt][nt][rr*2]   *= iq[mt*2+rr] * ikv[nt][0];
                acc[mt][nt][rr*2+1] *= iq[mt*2+rr] * ikv[nt][1];
            }

    float mx[4], mn[4];
#pragma unroll
    for (int i = 0; i < 4; i++) { mx[i] = -3.0e38f; mn[i] = 3.0e38f; }
#pragma unroll
    for (int mt = 0; mt < 2; mt++)
#pragma unroll
        for (int rr = 0; rr < 2; rr++) {
            int i = mt * 2 + rr;
#pragma unroll
            for (int nt = 0; nt < 8; nt++) {
                mx[i] = fmaxf(mx[i], fmaxf(acc[mt][nt][rr*2], acc[mt][nt][rr*2+1]));
                mn[i] = fminf(mn[i], fminf(acc[mt][nt][rr*2], acc[mt][nt][rr*2+1]));
            }
        }
#pragma unroll
    for (int o = 1; o <= 2; o <<= 1)
#pragma unroll
        for (int i = 0; i < 4; i++) {
            mx[i] = fmaxf(mx[i], __shfl_xor_sync(0xffffffffu, mx[i], o));
            mn[i] = fminf(mn[i], __shfl_xor_sync(0xffffffffu, mn[i], o));
        }

    float* sMx = (float*)dsm;          // [128][4]
    float* sMn = (float*)dsm + 512;
    if (cl == 0) {
#pragma unroll
        for (int i = 0; i < 4; i++) {
            int lr = m0 + (i >> 1) * 16 + (i & 1) * 8 + r;
            sMx[lr * 4 + nwarp] = mx[i];
            sMn[lr * 4 + nwarp] = mn[i];
        }
    }
    __syncthreads();
    float M1[4], M2[4];
#pragma unroll
    for (int i = 0; i < 4; i++) {
        int lr = m0 + (i >> 1) * 16 + (i & 1) * 8 + r;
        float vmx = sMx[lr*4], vmn = sMn[lr*4];
#pragma unroll
        for (int k = 1; k < 4; k++) {
            vmx = fmaxf(vmx, sMx[lr*4+k]);
            vmn = fminf(vmn, sMn[lr*4+k]);
        }
        M1[i] = (T1 >= 0.0f) ? T1 * vmx : T1 * vmn;
        M2[i] = (T2 >= 0.0f) ? T2 * vmx : T2 * vmn;
    }

    float s1[4] = {}, s2[4] = {};
#pragma unroll
    for (int mt = 0; mt < 2; mt++)
#pragma unroll
        for (int rr = 0; rr < 2; rr++) {
            int i = mt * 2 + rr;
            int lr = m0 + mt * 16 + rr * 8 + r;
            size_t rowoff = (size_t)(rowbase + lr) * 256;
#pragma unroll
            for (int nt = 0; nt < 8; nt++) {
                int col = n0 + nt * 8 + 2 * cl;
                float v0 = acc[mt][nt][rr*2], v1 = acc[mt][nt][rr*2+1];
                float e10 = __expf(v0 * T1 - M1[i]);
                float e11 = __expf(v1 * T1 - M1[i]);
                float e20 = __expf(v0 * T2 - M2[i]);
                float e21 = __expf(v1 * T2 - M2[i]);
                s1[i] += e10 + e11;
                s2[i] += e20 + e21;
                float2 o1, o2;
                o1.x = __uint_as_float(f2tf(e10)); o1.y = __uint_as_float(f2tf(e11));
                o2.x = __uint_as_float(f2tf(e20)); o2.y = __uint_as_float(f2tf(e21));
                *(float2*)(g_aH + rowoff + col) = o1;
                *(float2*)(g_aV + rowoff + col) = o2;
            }
        }
#pragma unroll
    for (int o = 1; o <= 2; o <<= 1)
#pragma unroll
        for (int i = 0; i < 4; i++) {
            s1[i] += __shfl_xor_sync(0xffffffffu, s1[i], o);
            s2[i] += __shfl_xor_sync(0xffffffffu, s2[i], o);
        }
    __syncthreads();
    float* sS1 = (float*)dsm;
    float* sS2 = (float*)dsm + 512;
    if (cl == 0) {
#pragma unroll
        for (int i = 0; i < 4; i++) {
            int lr = m0 + (i >> 1) * 16 + (i & 1) * 8 + r;
            sS1[lr * 4 + nwarp] = s1[i];
            sS2[lr * 4 + nwarp] = s2[i];
        }
    }
    __syncthreads();
    if (nwarp == 0 && cl == 0) {
#pragma unroll
        for (int i = 0; i < 4; i++) {
            int lr = m0 + (i >> 1) * 16 + (i & 1) * 8 + r;
            float tt1 = sS1[lr*4] + sS1[lr*4+1] + sS1[lr*4+2] + sS1[lr*4+3];
            float tt2 = sS2[lr*4] + sS2[lr*4+1] + sS2[lr*4+2] + sS2[lr*4+3];
            g_rs1[rowbase + lr] = tt1;
            g_rs2[rowbase + lr] = tt2;
        }
    }
}

// ---------------------------------------------------------------------------
// Kernel 3: x = (E1 @ vH)/rs1 + (E2 @ vV)/rs2, then FUSED output projection.
// __launch_bounds__(256,2): cap regs at 128 to keep 2 CTAs/SM.
// grid (64, 2, 16). Dyn smem 87040 B.
// ---------------------------------------------------------------------------
#define PVA(b,rr,cc) dsm[((b)*128 + (rr))*36 + (cc)]
#define PVB(b,rr,cc) dsm[2*128*36 + ((b)*32 + (rr))*136 + (cc)]
#define TOK(rr,cc)   dsm[(rr)*68 + (cc)]
#define WPS(rr,cc)   dsm[17408 + (rr)*68 + (cc)]

__global__ __launch_bounds__(256, 2) void k_pv(const float* __restrict__ Wp,
                                               const float* __restrict__ bp,
                                               float* __restrict__ out)
{
    extern __shared__ unsigned dsm[];
    const int t = threadIdx.x;
    const int lane = t & 31, warp = t >> 5;
    const int m0 = (warp >> 2) * 64, n0 = (warp & 3) * 32;
    const int r = lane >> 2, cl = lane & 3;
    const int bh = blockIdx.x, y = blockIdx.y, z = blockIdx.z;
    const int rowbase = bh * 256 + y * 128;

    float ratio[8];
#pragma unroll
    for (int i = 0; i < 8; i++) {
        int lr = m0 + (i >> 1) * 16 + (i & 1) * 8 + r;
        ratio[i] = __fdividef(g_rs2[rowbase + lr], g_rs1[rowbase + lr]);
    }

    float acc[4][4][4] = {};

    auto srcA = [&](int ch) -> const float* {
        return (ch < 8 ? g_aH : g_aV) + (size_t)rowbase * 256 + (ch & 7) * 32;
    };
    auto srcB = [&](int ch) -> const float* {
        return (ch < 8 ? g_vH : g_vV) + (size_t)bh * 524288
               + (size_t)((ch & 7) * 32) * 2048 + z * 128;
    };

    {
        const float* A = srcA(0); const float* Bp2 = srcB(0);
#pragma unroll
        for (int p = 0; p < 4; p++) {
            int lin = t + p * 256, row = lin >> 3, seg = lin & 7;
            cpa16(&PVA(0, row, seg * 4), A + (size_t)row * 256 + seg * 4);
        }
#pragma unroll
        for (int p = 0; p < 4; p++) {
            int lin = t + p * 256, row = lin >> 5, seg = lin & 31;
            cpa16(&PVB(0, row, seg * 4), Bp2 + (size_t)row * 2048 + seg * 4);
        }
        CP_COMMIT();
    }

    for (int ch = 0; ch < 16; ch++) {
        if (ch < 15) {
            int nb = (ch + 1) & 1;
            const float* A = srcA(ch + 1); const float* Bp2 = srcB(ch + 1);
#pragma unroll
            for (int p = 0; p < 4; p++) {
                int lin = t + p * 256, row = lin >> 3, seg = lin & 7;
                cpa16(&PVA(nb, row, seg * 4), A + (size_t)row * 256 + seg * 4);
            }
#pragma unroll
            for (int p = 0; p < 4; p++) {
                int lin = t + p * 256, row = lin >> 5, seg = lin & 31;
                cpa16(&PVB(nb, row, seg * 4), Bp2 + (size_t)row * 2048 + seg * 4);
            }
            CP_COMMIT();
            CP_WAIT1();
        } else {
            CP_WAIT0();
        }
        __syncthreads();
        const int buf = ch & 1;
#pragma unroll
        for (int kk = 0; kk < 32; kk += 8) {
            unsigned af[4][4], bf[4][2];
#pragma unroll
            for (int mt = 0; mt < 4; mt++) {
                int mr = m0 + mt * 16 + r;
                af[mt][0] = PVA(buf, mr, kk+cl);   af[mt][1] = PVA(buf, mr+8, kk+cl);
                af[mt][2] = PVA(buf, mr, kk+cl+4); af[mt][3] = PVA(buf, mr+8, kk+cl+4);
            }
#pragma unroll
            for (int nt = 0; nt < 4; nt++) {
                int nc = n0 + nt * 8 + r;
                bf[nt][0] = PVB(buf, kk+cl, nc); bf[nt][1] = PVB(buf, kk+cl+4, nc);
            }
#pragma unroll
            for (int mt = 0; mt < 4; mt++)
#pragma unroll
                for (int nt = 0; nt < 4; nt++)
                    mma_tf32(acc[mt][nt], af[mt][0], af[mt][1], af[mt][2], af[mt][3],
                             bf[nt][0], bf[nt][1]);
        }
        if (ch == 7) {
#pragma unroll
            for (int mt = 0; mt < 4; mt++)
#pragma unroll
                for (int rr = 0; rr < 2; rr++) {
                    float f = ratio[mt*2+rr];
#pragma unroll
                    for (int nt = 0; nt < 4; nt++) {
                        acc[mt][nt][rr*2]   *= f;
                        acc[mt][nt][rr*2+1] *= f;
                    }
                }
        }
        __syncthreads();
    }

    // -------- stage normalized x rows as 256 complete tokens + load Wp ------
    __syncthreads();
    const int half = (n0 >= 64) ? 1 : 0;
#pragma unroll
    for (int mt = 0; mt < 4; mt++) {
#pragma unroll
        for (int rr = 0; rr < 2; rr++) {
            int s_local = m0 + mt * 16 + rr * 8 + r;
            float f = __fdividef(1.0f, g_rs2[rowbase + s_local]);
            int tt = s_local * 2 + half;
#pragma unroll
            for (int nt = 0; nt < 4; nt++) {
                int c = ((n0 & 63) + nt * 8 + 2 * cl);
                TOK(tt, c)   = f2tf(acc[mt][nt][rr*2]   * f);
                TOK(tt, c+1) = f2tf(acc[mt][nt][rr*2+1] * f);
            }
        }
    }
    for (int i = t; i < 1024; i += 256) {
        int row = i >> 4, c4 = (i & 15) << 2;
        float4 w4 = *(const float4*)(Wp + (size_t)row * 64 + c4);
        WPS(row, c4) = f2tf(w4.x); WPS(row, c4+1) = f2tf(w4.y);
        WPS(row, c4+2) = f2tf(w4.z); WPS(row, c4+3) = f2tf(w4.w);
    }
    __syncthreads();

    // -------- fused projection: each warp projects 32 token rows ------------
    float acc2[2][8][4] = {};
    const int tt0 = warp * 32;
#pragma unroll
    for (int kk = 0; kk < 64; kk += 8) {
        unsigned af[2][4], bf[8][2];
#pragma unroll
        for (int mt = 0; mt < 2; mt++) {
            int mr = tt0 + mt * 16 + r;
            af[mt][0] = TOK(mr, kk+cl);   af[mt][1] = TOK(mr+8, kk+cl);
            af[mt][2] = TOK(mr, kk+cl+4); af[mt][3] = TOK(mr+8, kk+cl+4);
        }
#pragma unroll
        for (int nt = 0; nt < 8; nt++) {
            int nr = nt * 8 + r;
            bf[nt][0] = WPS(nr, kk+cl); bf[nt][1] = WPS(nr, kk+cl+4);
        }
#pragma unroll
        for (int mt = 0; mt < 2; mt++)
#pragma unroll
            for (int nt = 0; nt < 8; nt++)
                mma_tf32(acc2[mt][nt], af[mt][0], af[mt][1], af[mt][2], af[mt][3],
                         bf[nt][0], bf[nt][1]);
    }

    const int b = bh >> 3, h = bh & 7;
#pragma unroll
    for (int mt = 0; mt < 2; mt++) {
#pragma unroll
        for (int rr = 0; rr < 2; rr++) {
            int tt = tt0 + mt * 16 + rr * 8 + r;
            int s = y * 128 + (tt >> 1);
            int nn = h * 32 + 2 * z + (tt & 1);
            size_t rowoff = ((size_t)b * 65536 + (size_t)s * 256 + nn) * 64;
#pragma unroll
            for (int nt = 0; nt < 8; nt++) {
                int c = nt * 8 + 2 * cl;
                float2 bv = *(const float2*)(bp + c);
                float2 o;
                o.x = acc2[mt][nt][rr*2]   + bv.x;
                o.y = acc2[mt][nt][rr*2+1] + bv.y;
                *(float2*)(out + rowoff + c) = o;
            }
        }
    }
}

// ---------------------------------------------------------------------------
extern "C" void kernel_launch(void* const* d_in, const int* in_sizes, int n_in,
                              void* d_out, int out_size)
{
    const float* x      = (const float*)d_in[0];
    const float* qkv_w  = (const float*)d_in[1];
    const float* qkv_b  = (const float*)d_in[2];
    const float* proj_w = (const float*)d_in[3];
    const float* proj_b = (const float*)d_in[4];
    const float* t1     = (const float*)d_in[5];
    const float* t2     = (const float*)d_in[6];
    float* out          = (float*)d_out;

    cudaFuncSetAttribute(k_simsm, cudaFuncAttributeMaxDynamicSharedMemorySize, 208896);
    cudaFuncSetAttribute(k_pv,    cudaFuncAttributeMaxDynamicSharedMemorySize, 87040);

    k_zero<<<16, 1024>>>();
    k_qkv<<<dim3(4096, 2), 256>>>(x, qkv_w, qkv_b);
    k_simsm<<<dim3(64, 2), 512, 208896>>>(t1, t2);
    k_pv<<<dim3(64, 2, 16), 256, 87040>>>(proj_w, proj_b, out);
}

// round 9
// speedup vs baseline: 4.1252x; 1.0053x over previous
#include <cuda_runtime.h>
#include <math.h>

// B=8, S=256, N=256, C=64, NH=8, D=2048
#define BB 8
#define SS 256

// Scratch (device globals). q/k/vH/vV/aH/aV stored pre-rounded to tf32.
__device__ float g_q [(size_t)BB*8*SS*2048];
__device__ float g_k [(size_t)BB*8*SS*2048];
__device__ float g_vH[(size_t)BB*8*SS*2048];
__device__ float g_vV[(size_t)BB*8*SS*2048];
__device__ float g_inq[BB*8*SS];              // sum of squares (q rows)
__device__ float g_ink[BB*8*SS];              // sum of squares (k rows)
__device__ float g_aH [(size_t)BB*8*SS*SS];   // unnormalized exp
__device__ float g_aV [(size_t)BB*8*SS*SS];
__device__ float g_rs1[BB*8*SS];              // softmax row sums
__device__ float g_rs2[BB*8*SS];

__device__ __forceinline__ unsigned f2tf(float f) {
    unsigned u;
    asm("cvt.rna.tf32.f32 %0, %1;" : "=r"(u) : "f"(f));
    return u;
}

__device__ __forceinline__ void mma_tf32(float* c, unsigned a0, unsigned a1,
                                         unsigned a2, unsigned a3,
                                         unsigned b0, unsigned b1) {
    asm volatile(
        "mma.sync.aligned.m16n8k8.row.col.f32.tf32.tf32.f32 "
        "{%0,%1,%2,%3}, {%4,%5,%6,%7}, {%8,%9}, {%0,%1,%2,%3};"
        : "+f"(c[0]), "+f"(c[1]), "+f"(c[2]), "+f"(c[3])
        : "r"(a0), "r"(a1), "r"(a2), "r"(a3), "r"(b0), "r"(b1));
}

// ldmatrix x4: loads 4 8x8 b16 tiles == 4 8x4 b32 tiles. For tf32 fragments
// from [row][k] smem: d0=A[r][c], d1=A[r+8][c], d2=A[r][c+4], d3=A[r+8][c+4].
__device__ __forceinline__ void ldsm4(unsigned* d, const void* p) {
    unsigned a = (unsigned)__cvta_generic_to_shared(p);
    asm volatile("ldmatrix.sync.aligned.m8n8.x4.shared.b16 {%0,%1,%2,%3}, [%4];"
        : "=r"(d[0]), "=r"(d[1]), "=r"(d[2]), "=r"(d[3]) : "r"(a));
}

__device__ __forceinline__ void cpa16(void* s, const void* g) {
    unsigned sa = (unsigned)__cvta_generic_to_shared(s);
    asm volatile("cp.async.cg.shared.global [%0], [%1], 16;" :: "r"(sa), "l"(g));
}
#define CP_COMMIT() asm volatile("cp.async.commit_group;")
#define CP_WAIT1()  asm volatile("cp.async.wait_group 1;")
#define CP_WAIT0()  asm volatile("cp.async.wait_group 0;")

// ---------------------------------------------------------------------------
// Kernel 0: zero the sumsq accumulators
// ---------------------------------------------------------------------------
__global__ void k_zero()
{
    int i = blockIdx.x * 1024 + threadIdx.x;
    if (i < 16384) { g_inq[i] = 0.0f; g_ink[i] = 0.0f; }
}

// ---------------------------------------------------------------------------
// Kernel 1: QKV GEMM (tf32 MMA + ldmatrix), scatter + tf32-round at write,
// fused q/k row sum-of-squares via shuffle-reduce + atomicAdd.
// ---------------------------------------------------------------------------
__global__ __launch_bounds__(256, 2) void k_qkv(const float* __restrict__ X,
                                                const float* __restrict__ W,
                                                const float* __restrict__ bias)
{
    __shared__ unsigned sA[128][36];
    __shared__ unsigned sB[128][36];
    const int t = threadIdx.x;
    const int lane = t & 31, warp = t >> 5;
    const int m0 = (warp >> 2) * 64, n0 = (warp & 3) * 32;
    const int r = lane >> 2, cl = lane & 3;
    const int grp = lane >> 3, li = lane & 7;
    const int arow = (grp & 1) * 8 + li;       // ldmatrix lane row
    const int acol4 = (grp >> 1) * 4;          // ldmatrix lane col offset
    const size_t T0 = (size_t)blockIdx.x * 128;
    const int f0 = blockIdx.y * 128;

    float acc[4][4][4] = {};

    for (int k0 = 0; k0 < 64; k0 += 32) {
#pragma unroll
        for (int p = 0; p < 4; p++) {
            int row = (t >> 3) + p * 32, c4 = (t & 7) << 2;
            float4 v = *(const float4*)(X + (T0 + row) * 64 + k0 + c4);
            sA[row][c4] = f2tf(v.x); sA[row][c4+1] = f2tf(v.y);
            sA[row][c4+2] = f2tf(v.z); sA[row][c4+3] = f2tf(v.w);
            float4 w4 = *(const float4*)(W + (size_t)(f0 + row) * 64 + k0 + c4);
            sB[row][c4] = f2tf(w4.x); sB[row][c4+1] = f2tf(w4.y);
            sB[row][c4+2] = f2tf(w4.z); sB[row][c4+3] = f2tf(w4.w);
        }
        __syncthreads();
#pragma unroll
        for (int kk = 0; kk < 32; kk += 8) {
            unsigned af[4][4], bf[4][2];
#pragma unroll
            for (int mt = 0; mt < 4; mt++)
                ldsm4(af[mt], &sA[m0 + mt * 16 + arow][kk + acol4]);
#pragma unroll
            for (int np = 0; np < 2; np++) {
                unsigned d[4];
                ldsm4(d, &sB[n0 + np * 16 + arow][kk + acol4]);
                bf[np*2][0] = d[0]; bf[np*2+1][0] = d[1];
                bf[np*2][1] = d[2]; bf[np*2+1][1] = d[3];
            }
#pragma unroll
            for (int mt = 0; mt < 4; mt++)
#pragma unroll
                for (int nt = 0; nt < 4; nt++)
                    mma_tf32(acc[mt][nt], af[mt][0], af[mt][1], af[mt][2], af[mt][3],
                             bf[nt][0], bf[nt][1]);
        }
        __syncthreads();
    }

#pragma unroll
    for (int mt = 0; mt < 4; mt++) {
#pragma unroll
        for (int rr = 0; rr < 2; rr++) {
            size_t T = T0 + m0 + mt * 16 + r + rr * 8;
            int b = (int)(T >> 16);
            int s = (int)((T >> 8) & 255);
            int n = (int)(T & 255);
            int g = n >> 6;
            int h = (n >> 3) & 7;
            float ssq = 0.0f;
#pragma unroll
            for (int nt = 0; nt < 4; nt++) {
                int f = f0 + n0 + nt * 8 + 2 * cl;
                float2 bv = *(const float2*)(bias + f);
                float a0 = acc[mt][nt][rr*2]   + bv.x;
                float a1 = acc[mt][nt][rr*2+1] + bv.y;
                ssq += a0 * a0 + a1 * a1;
                float2 val;
                val.x = __uint_as_float(f2tf(a0));
                val.y = __uint_as_float(f2tf(a1));
                int d0 = ((n & 7) << 8) + f;
                float* dst; size_t idx;
                if (g == 3) {
                    int h2 = s >> 5;
                    int s2 = h * 32 + (d0 >> 6);
                    int d2 = ((s & 31) << 6) + (d0 & 63);
                    dst = g_vV;
                    idx = (((size_t)(b * 8 + h2) * 256 + s2) << 11) + d2;
                } else {
                    dst = (g == 0) ? g_q : (g == 1 ? g_k : g_vH);
                    idx = (((size_t)(b * 8 + h) * 256 + s) << 11) + d0;
                }
                *(float2*)(dst + idx) = val;
            }
            if (g < 2) {
                ssq += __shfl_xor_sync(0xffffffffu, ssq, 1);
                ssq += __shfl_xor_sync(0xffffffffu, ssq, 2);
                if (cl == 0)
                    atomicAdd((g == 0 ? g_inq : g_ink) + (b * 8 + h) * 256 + s, ssq);
            }
        }
    }
}

// ---------------------------------------------------------------------------
// Kernel 2: fused sim + dual softmax. Tile 128x256, grid (64,2), 512 threads.
// ldmatrix fragment loads; kc=64 double-buffered cp.async.
// ---------------------------------------------------------------------------
#define SIMQ(b,rr,cc) dsm[((b)*128 + (rr))*68 + (cc)]
#define SIMK(b,rr,cc) dsm[2*128*68 + ((b)*256 + (rr))*68 + (cc)]

__global__ __launch_bounds__(512, 1) void k_simsm(const float* __restrict__ t1p,
                                                  const float* __restrict__ t2p)
{
    extern __shared__ unsigned dsm[];
    const int t = threadIdx.x;
    const int lane = t & 31, warp = t >> 5;
    const int m0 = (warp >> 2) * 32;
    const int nwarp = warp & 3;
    const int n0 = nwarp * 64;
    const int r = lane >> 2, cl = lane & 3;
    const int grp = lane >> 3, li = lane & 7;
    const int arow = (grp & 1) * 8 + li;
    const int acol4 = (grp >> 1) * 4;
    const int bh = blockIdx.x, y = blockIdx.y;
    const float* Qb = g_q + ((size_t)bh * 256 + y * 128) * 2048;
    const float* Kb = g_k + (size_t)bh * 256 * 2048;

    float acc[2][8][4] = {};

    {
#pragma unroll
        for (int p = 0; p < 4; p++) {
            int lin = t + p * 512, row = lin >> 4, seg = lin & 15;
            cpa16(&SIMQ(0, row, seg * 4), Qb + (size_t)row * 2048 + seg * 4);
        }
#pragma unroll
        for (int p = 0; p < 8; p++) {
            int lin = t + p * 512, row = lin >> 4, seg = lin & 15;
            cpa16(&SIMK(0, row, seg * 4), Kb + (size_t)row * 2048 + seg * 4);
        }
        CP_COMMIT();
    }

    for (int ch = 0; ch < 32; ch++) {
        if (ch < 31) {
            int nb = (ch + 1) & 1, k0 = (ch + 1) * 64;
#pragma unroll
            for (int p = 0; p < 4; p++) {
                int lin = t + p * 512, row = lin >> 4, seg = lin & 15;
                cpa16(&SIMQ(nb, row, seg * 4), Qb + (size_t)row * 2048 + k0 + seg * 4);
            }
#pragma unroll
            for (int p = 0; p < 8; p++) {
                int lin = t + p * 512, row = lin >> 4, seg = lin & 15;
                cpa16(&SIMK(nb, row, seg * 4), Kb + (size_t)row * 2048 + k0 + seg * 4);
            }
            CP_COMMIT();
            CP_WAIT1();
        } else {
            CP_WAIT0();
        }
        __syncthreads();
        const int buf = ch & 1;
#pragma unroll
        for (int kk = 0; kk < 64; kk += 8) {
            unsigned af[2][4], bf[8][2];
#pragma unroll
            for (int mt = 0; mt < 2; mt++)
                ldsm4(af[mt], &SIMQ(buf, m0 + mt * 16 + arow, kk + acol4));
#pragma unroll
            for (int np = 0; np < 4; np++) {
                unsigned d[4];
                ldsm4(d, &SIMK(buf, n0 + np * 16 + arow, kk + acol4));
                bf[np*2][0] = d[0]; bf[np*2+1][0] = d[1];
                bf[np*2][1] = d[2]; bf[np*2+1][1] = d[3];
            }
#pragma unroll
            for (int mt = 0; mt < 2; mt++)
#pragma unroll
                for (int nt = 0; nt < 8; nt++)
                    mma_tf32(acc[mt][nt], af[mt][0], af[mt][1], af[mt][2], af[mt][3],
                             bf[nt][0], bf[nt][1]);
        }
        __syncthreads();
    }

    // ---------------- epilogue: scale + dual softmax ----------------
    const int h = bh & 7;
    const float T1 = t1p[h], T2 = t2p[h];
    const int rowbase = bh * 256 + y * 128;

    float iq[4];
#pragma unroll
    for (int i = 0; i < 4; i++) {
        float ssq = g_inq[rowbase + m0 + (i >> 1) * 16 + (i & 1) * 8 + r];
        iq[i] = 1.0f / fmaxf(sqrtf(ssq), 1e-12f);
    }
    float ikv[8][2];
#pragma unroll
    for (int nt = 0; nt < 8; nt++) {
        float2 v2 = *(const float2*)(g_ink + bh * 256 + n0 + nt * 8 + 2 * cl);
        ikv[nt][0] = 1.0f / fmaxf(sqrtf(v2.x), 1e-12f);
        ikv[nt][1] = 1.0f / fmaxf(sqrtf(v2.y), 1e-12f);
    }
#pragma unroll
    for (int mt = 0; mt < 2; mt++)
#pragma unroll
        for (int nt = 0; nt < 8; nt++)
#pragma unroll
            for (int rr = 0; rr < 2; rr++) {
                acc[mt][nt][rr*2]   *= iq[mt*2+rr] * ikv[nt][0];
                acc[mt][nt][rr*2+1] *= iq[mt*2+rr] * ikv[nt][1];
            }

    float mx[4], mn[4];
#pragma unroll
    for (int i = 0; i < 4; i++) { mx[i] = -3.0e38f; mn[i] = 3.0e38f; }
#pragma unroll
    for (int mt = 0; mt < 2; mt++)
#pragma unroll
        for (int rr = 0; rr < 2; rr++) {
            int i = mt * 2 + rr;
#pragma unroll
            for (int nt = 0; nt < 8; nt++) {
                mx[i] = fmaxf(mx[i], fmaxf(acc[mt][nt][rr*2], acc[mt][nt][rr*2+1]));
                mn[i] = fminf(mn[i], fminf(acc[mt][nt][rr*2], acc[mt][nt][rr*2+1]));
            }
        }
#pragma unroll
    for (int o = 1; o <= 2; o <<= 1)
#pragma unroll
        for (int i = 0; i < 4; i++) {
            mx[i] = fmaxf(mx[i], __shfl_xor_sync(0xffffffffu, mx[i], o));
            mn[i] = fminf(mn[i], __shfl_xor_sync(0xffffffffu, mn[i], o));
        }

    float* sMx = (float*)dsm;          // [128][4]
    float* sMn = (float*)dsm + 512;
    if (cl == 0) {
#pragma unroll
        for (int i = 0; i < 4; i++) {
            int lr = m0 + (i >> 1) * 16 + (i & 1) * 8 + r;
            sMx[lr * 4 + nwarp] = mx[i];
            sMn[lr * 4 + nwarp] = mn[i];
        }
    }
    __syncthreads();
    float M1[4], M2[4];
#pragma unroll
    for (int i = 0; i < 4; i++) {
        int lr = m0 + (i >> 1) * 16 + (i & 1) * 8 + r;
        float vmx = sMx[lr*4], vmn = sMn[lr*4];
#pragma unroll
        for (int k = 1; k < 4; k++) {
            vmx = fmaxf(vmx, sMx[lr*4+k]);
            vmn = fminf(vmn, sMn[lr*4+k]);
        }
        M1[i] = (T1 >= 0.0f) ? T1 * vmx : T1 * vmn;
        M2[i] = (T2 >= 0.0f) ? T2 * vmx : T2 * vmn;
    }

    float s1[4] = {}, s2[4] = {};
#pragma unroll
    for (int mt = 0; mt < 2; mt++)
#pragma unroll
        for (int rr = 0; rr < 2; rr++) {
            int i = mt * 2 + rr;
            int lr = m0 + mt * 16 + rr * 8 + r;
            size_t rowoff = (size_t)(rowbase + lr) * 256;
#pragma unroll
            for (int nt = 0; nt < 8; nt++) {
                int col = n0 + nt * 8 + 2 * cl;
                float v0 = acc[mt][nt][rr*2], v1 = acc[mt][nt][rr*2+1];
                float e10 = __expf(v0 * T1 - M1[i]);
                float e11 = __expf(v1 * T1 - M1[i]);
                float e20 = __expf(v0 * T2 - M2[i]);
                float e21 = __expf(v1 * T2 - M2[i]);
                s1[i] += e10 + e11;
                s2[i] += e20 + e21;
                float2 o1, o2;
                o1.x = __uint_as_float(f2tf(e10)); o1.y = __uint_as_float(f2tf(e11));
                o2.x = __uint_as_float(f2tf(e20)); o2.y = __uint_as_float(f2tf(e21));
                *(float2*)(g_aH + rowoff + col) = o1;
                *(float2*)(g_aV + rowoff + col) = o2;
            }
        }
#pragma unroll
    for (int o = 1; o <= 2; o <<= 1)
#pragma unroll
        for (int i = 0; i < 4; i++) {
            s1[i] += __shfl_xor_sync(0xffffffffu, s1[i], o);
            s2[i] += __shfl_xor_sync(0xffffffffu, s2[i], o);
        }
    __syncthreads();
    float* sS1 = (float*)dsm;
    float* sS2 = (float*)dsm + 512;
    if (cl == 0) {
#pragma unroll
        for (int i = 0; i < 4; i++) {
            int lr = m0 + (i >> 1) * 16 + (i & 1) * 8 + r;
            sS1[lr * 4 + nwarp] = s1[i];
            sS2[lr * 4 + nwarp] = s2[i];
        }
    }
    __syncthreads();
    if (nwarp == 0 && cl == 0) {
#pragma unroll
        for (int i = 0; i < 4; i++) {
            int lr = m0 + (i >> 1) * 16 + (i & 1) * 8 + r;
            float tt1 = sS1[lr*4] + sS1[lr*4+1] + sS1[lr*4+2] + sS1[lr*4+3];
            float tt2 = sS2[lr*4] + sS2[lr*4+1] + sS2[lr*4+2] + sS2[lr*4+3];
            g_rs1[rowbase + lr] = tt1;
            g_rs2[rowbase + lr] = tt2;
        }
    }
}

// ---------------------------------------------------------------------------
// Kernel 3: x = (E1 @ vH)/rs1 + (E2 @ vV)/rs2, then FUSED output projection.
// ldmatrix for A-side fragments; B stays scalar ([k][n] layout).
// grid (64, 2, 16). Dyn smem 87040 B.
// ---------------------------------------------------------------------------
#define PVA(b,rr,cc) dsm[((b)*128 + (rr))*36 + (cc)]
#define PVB(b,rr,cc) dsm[2*128*36 + ((b)*32 + (rr))*136 + (cc)]
#define TOK(rr,cc)   dsm[(rr)*68 + (cc)]
#define WPS(rr,cc)   dsm[17408 + (rr)*68 + (cc)]

__global__ __launch_bounds__(256, 2) void k_pv(const float* __restrict__ Wp,
                                               const float* __restrict__ bp,
                                               float* __restrict__ out)
{
    extern __shared__ unsigned dsm[];
    const int t = threadIdx.x;
    const int lane = t & 31, warp = t >> 5;
    const int m0 = (warp >> 2) * 64, n0 = (warp & 3) * 32;
    const int r = lane >> 2, cl = lane & 3;
    const int grp = lane >> 3, li = lane & 7;
    const int arow = (grp & 1) * 8 + li;
    const int acol4 = (grp >> 1) * 4;
    const int bh = blockIdx.x, y = blockIdx.y, z = blockIdx.z;
    const int rowbase = bh * 256 + y * 128;

    float ratio[8];
#pragma unroll
    for (int i = 0; i < 8; i++) {
        int lr = m0 + (i >> 1) * 16 + (i & 1) * 8 + r;
        ratio[i] = __fdividef(g_rs2[rowbase + lr], g_rs1[rowbase + lr]);
    }

    float acc[4][4][4] = {};

    auto srcA = [&](int ch) -> const float* {
        return (ch < 8 ? g_aH : g_aV) + (size_t)rowbase * 256 + (ch & 7) * 32;
    };
    auto srcB = [&](int ch) -> const float* {
        return (ch < 8 ? g_vH : g_vV) + (size_t)bh * 524288
               + (size_t)((ch & 7) * 32) * 2048 + z * 128;
    };

    {
        const float* A = srcA(0); const float* Bp2 = srcB(0);
#pragma unroll
        for (int p = 0; p < 4; p++) {
            int lin = t + p * 256, row = lin >> 3, seg = lin & 7;
            cpa16(&PVA(0, row, seg * 4), A + (size_t)row * 256 + seg * 4);
        }
#pragma unroll
        for (int p = 0; p < 4; p++) {
            int lin = t + p * 256, row = lin >> 5, seg = lin & 31;
            cpa16(&PVB(0, row, seg * 4), Bp2 + (size_t)row * 2048 + seg * 4);
        }
        CP_COMMIT();
    }

    for (int ch = 0; ch < 16; ch++) {
        if (ch < 15) {
            int nb = (ch + 1) & 1;
            const float* A = srcA(ch + 1); const float* Bp2 = srcB(ch + 1);
#pragma unroll
            for (int p = 0; p < 4; p++) {
                int lin = t + p * 256, row = lin >> 3, seg = lin & 7;
                cpa16(&PVA(nb, row, seg * 4), A + (size_t)row * 256 + seg * 4);
            }
#pragma unroll
            for (int p = 0; p < 4; p++) {
                int lin = t + p * 256, row = lin >> 5, seg = lin & 31;
                cpa16(&PVB(nb, row, seg * 4), Bp2 + (size_t)row * 2048 + seg * 4);
            }
            CP_COMMIT();
            CP_WAIT1();
        } else {
            CP_WAIT0();
        }
        __syncthreads();
        const int buf = ch & 1;
#pragma unroll
        for (int kk = 0; kk < 32; kk += 8) {
            unsigned af[4][4], bf[4][2];
#pragma unroll
            for (int mt = 0; mt < 4; mt++)
                ldsm4(af[mt], &PVA(buf, m0 + mt * 16 + arow, kk + acol4));
#pragma unroll
            for (int nt = 0; nt < 4; nt++) {
                int nc = n0 + nt * 8 + r;
                bf[nt][0] = PVB(buf, kk+cl, nc); bf[nt][1] = PVB(buf, kk+cl+4, nc);
            }
#pragma unroll
            for (int mt = 0; mt < 4; mt++)
#pragma unroll
                for (int nt = 0; nt < 4; nt++)
                    mma_tf32(acc[mt][nt], af[mt][0], af[mt][1], af[mt][2], af[mt][3],
                             bf[nt][0], bf[nt][1]);
        }
        if (ch == 7) {
#pragma unroll
            for (int mt = 0; mt < 4; mt++)
#pragma unroll
                for (int rr = 0; rr < 2; rr++) {
                    float f = ratio[mt*2+rr];
#pragma unroll
                    for (int nt = 0; nt < 4; nt++) {
                        acc[mt][nt][rr*2]   *= f;
                        acc[mt][nt][rr*2+1] *= f;
                    }
                }
        }
        __syncthreads();
    }

    // -------- stage normalized x rows as 256 complete tokens + load Wp ------
    __syncthreads();
    const int half = (n0 >= 64) ? 1 : 0;
#pragma unroll
    for (int mt = 0; mt < 4; mt++) {
#pragma unroll
        for (int rr = 0; rr < 2; rr++) {
            int s_local = m0 + mt * 16 + rr * 8 + r;
            float f = __fdividef(1.0f, g_rs2[rowbase + s_local]);
            int tt = s_local * 2 + half;
#pragma unroll
            for (int nt = 0; nt < 4; nt++) {
                int c = ((n0 & 63) + nt * 8 + 2 * cl);
                TOK(tt, c)   = f2tf(acc[mt][nt][rr*2]   * f);
                TOK(tt, c+1) = f2tf(acc[mt][nt][rr*2+1] * f);
            }
        }
    }
    for (int i = t; i < 1024; i += 256) {
        int row = i >> 4, c4 = (i & 15) << 2;
        float4 w4 = *(const float4*)(Wp + (size_t)row * 64 + c4);
        WPS(row, c4) = f2tf(w4.x); WPS(row, c4+1) = f2tf(w4.y);
        WPS(row, c4+2) = f2tf(w4.z); WPS(row, c4+3) = f2tf(w4.w);
    }
    __syncthreads();

    // -------- fused projection: each warp projects 32 token rows ------------
    float acc2[2][8][4] = {};
    const int tt0 = warp * 32;
#pragma unroll
    for (int kk = 0; kk < 64; kk += 8) {
        unsigned af[2][4], bf[8][2];
#pragma unroll
        for (int mt = 0; mt < 2; mt++)
            ldsm4(af[mt], &TOK(tt0 + mt * 16 + arow, kk + acol4));
#pragma unroll
        for (int np = 0; np < 4; np++) {
            unsigned d[4];
            ldsm4(d, &WPS(np * 16 + arow, kk + acol4));
            bf[np*2][0] = d[0]; bf[np*2+1][0] = d[1];
            bf[np*2][1] = d[2]; bf[np*2+1][1] = d[3];
        }
#pragma unroll
        for (int mt = 0; mt < 2; mt++)
#pragma unroll
            for (int nt = 0; nt < 8; nt++)
                mma_tf32(acc2[mt][nt], af[mt][0], af[mt][1], af[mt][2], af[mt][3],
                         bf[nt][0], bf[nt][1]);
    }

    const int b = bh >> 3, h = bh & 7;
#pragma unroll
    for (int mt = 0; mt < 2; mt++) {
#pragma unroll
        for (int rr = 0; rr < 2; rr++) {
            int tt = tt0 + mt * 16 + rr * 8 + r;
            int s = y * 128 + (tt >> 1);
            int nn = h * 32 + 2 * z + (tt & 1);
            size_t rowoff = ((size_t)b * 65536 + (size_t)s * 256 + nn) * 64;
#pragma unroll
            for (int nt = 0; nt < 8; nt++) {
                int c = nt * 8 + 2 * cl;
                float2 bv = *(const float2*)(bp + c);
                float2 o;
                o.x = acc2[mt][nt][rr*2]   + bv.x;
                o.y = acc2[mt][nt][rr*2+1] + bv.y;
                *(float2*)(out + rowoff + c) = o;
            }
        }
    }
}

// ---------------------------------------------------------------------------
extern "C" void kernel_launch(void* const* d_in, const int* in_sizes, int n_in,
                              void* d_out, int out_size)
{
    const float* x      = (const float*)d_in[0];
    const float* qkv_w  = (const float*)d_in[1];
    const float* qkv_b  = (const float*)d_in[2];
    const float* proj_w = (const float*)d_in[3];
    const float* proj_b = (const float*)d_in[4];
    const float* t1     = (const float*)d_in[5];
    const float* t2     = (const float*)d_in[6];
    float* out          = (float*)d_out;

    cudaFuncSetAttribute(k_simsm, cudaFuncAttributeMaxDynamicSharedMemorySize, 208896);
    cudaFuncSetAttribute(k_pv,    cudaFuncAttributeMaxDynamicSharedMemorySize, 87040);

    k_zero<<<16, 1024>>>();
    k_qkv<<<dim3(4096, 2), 256>>>(x, qkv_w, qkv_b);
    k_simsm<<<dim3(64, 2), 512, 208896>>>(t1, t2);
    k_pv<<<dim3(64, 2, 16), 256, 87040>>>(proj_w, proj_b, out);
}

// round 10
// speedup vs baseline: 4.6440x; 1.1258x over previous
#include <cuda_runtime.h>
#include <cuda_bf16.h>
#include <math.h>

// B=8, S=256, N=256, C=64, NH=8, D=2048
#define BB 8
#define SS 256

// Scratch. q/k stored bf16; vH/vV/aH/aV stored tf32-rounded fp32.
__device__ unsigned short g_qh[(size_t)BB*8*SS*2048];
__device__ unsigned short g_kh[(size_t)BB*8*SS*2048];
__device__ float g_vH[(size_t)BB*8*SS*2048];
__device__ float g_vV[(size_t)BB*8*SS*2048];
__device__ float g_inq[BB*8*SS];              // sum of squares (q rows)
__device__ float g_ink[BB*8*SS];              // sum of squares (k rows)
__device__ float g_aH [(size_t)BB*8*SS*SS];   // unnormalized exp
__device__ float g_aV [(size_t)BB*8*SS*SS];
__device__ float g_rs1[BB*8*SS];              // softmax row sums
__device__ float g_rs2[BB*8*SS];

__device__ __forceinline__ unsigned f2tf(float f) {
    unsigned u;
    asm("cvt.rna.tf32.f32 %0, %1;" : "=r"(u) : "f"(f));
    return u;
}

__device__ __forceinline__ unsigned pack_bf16(float a, float b) {
    __nv_bfloat162 h = __floats2bfloat162_rn(a, b);   // .x = a (low half)
    return *(unsigned*)&h;
}

__device__ __forceinline__ void mma_tf32(float* c, unsigned a0, unsigned a1,
                                         unsigned a2, unsigned a3,
                                         unsigned b0, unsigned b1) {
    asm volatile(
        "mma.sync.aligned.m16n8k8.row.col.f32.tf32.tf32.f32 "
        "{%0,%1,%2,%3}, {%4,%5,%6,%7}, {%8,%9}, {%0,%1,%2,%3};"
        : "+f"(c[0]), "+f"(c[1]), "+f"(c[2]), "+f"(c[3])
        : "r"(a0), "r"(a1), "r"(a2), "r"(a3), "r"(b0), "r"(b1));
}

__device__ __forceinline__ void mma_bf16(float* c, unsigned a0, unsigned a1,
                                         unsigned a2, unsigned a3,
                                         unsigned b0, unsigned b1) {
    asm volatile(
        "mma.sync.aligned.m16n8k16.row.col.f32.bf16.bf16.f32 "
        "{%0,%1,%2,%3}, {%4,%5,%6,%7}, {%8,%9}, {%0,%1,%2,%3};"
        : "+f"(c[0]), "+f"(c[1]), "+f"(c[2]), "+f"(c[3])
        : "r"(a0), "r"(a1), "r"(a2), "r"(a3), "r"(b0), "r"(b1));
}

// ldmatrix x4 from [row][k] smem (works for 8x4xb32 tiles and 8x8xb16 tiles)
__device__ __forceinline__ void ldsm4(unsigned* d, const void* p) {
    unsigned a = (unsigned)__cvta_generic_to_shared(p);
    asm volatile("ldmatrix.sync.aligned.m8n8.x4.shared.b16 {%0,%1,%2,%3}, [%4];"
        : "=r"(d[0]), "=r"(d[1]), "=r"(d[2]), "=r"(d[3]) : "r"(a));
}

__device__ __forceinline__ void cpa16(void* s, const void* g) {
    unsigned sa = (unsigned)__cvta_generic_to_shared(s);
    asm volatile("cp.async.cg.shared.global [%0], [%1], 16;" :: "r"(sa), "l"(g));
}
#define CP_COMMIT() asm volatile("cp.async.commit_group;")
#define CP_WAIT1()  asm volatile("cp.async.wait_group 1;")
#define CP_WAIT0()  asm volatile("cp.async.wait_group 0;")

// ---------------------------------------------------------------------------
// Kernel 0: zero the sumsq accumulators
// ---------------------------------------------------------------------------
__global__ void k_zero()
{
    int i = blockIdx.x * 1024 + threadIdx.x;
    if (i < 16384) { g_inq[i] = 0.0f; g_ink[i] = 0.0f; }
}

// ---------------------------------------------------------------------------
// Kernel 1: QKV GEMM (tf32 MMA + ldmatrix). q/k stored bf16, vH/vV tf32.
// Fused q/k row sum-of-squares (from fp32 values) via shuffle + atomicAdd.
// ---------------------------------------------------------------------------
__global__ __launch_bounds__(256, 2) void k_qkv(const float* __restrict__ X,
                                                const float* __restrict__ W,
                                                const float* __restrict__ bias)
{
    __shared__ unsigned sA[128][36];
    __shared__ unsigned sB[128][36];
    const int t = threadIdx.x;
    const int lane = t & 31, warp = t >> 5;
    const int m0 = (warp >> 2) * 64, n0 = (warp & 3) * 32;
    const int r = lane >> 2, cl = lane & 3;
    const int grp = lane >> 3, li = lane & 7;
    const int arow = (grp & 1) * 8 + li;
    const int acol4 = (grp >> 1) * 4;
    const size_t T0 = (size_t)blockIdx.x * 128;
    const int f0 = blockIdx.y * 128;

    float acc[4][4][4] = {};

    for (int k0 = 0; k0 < 64; k0 += 32) {
#pragma unroll
        for (int p = 0; p < 4; p++) {
            int row = (t >> 3) + p * 32, c4 = (t & 7) << 2;
            float4 v = *(const float4*)(X + (T0 + row) * 64 + k0 + c4);
            sA[row][c4] = f2tf(v.x); sA[row][c4+1] = f2tf(v.y);
            sA[row][c4+2] = f2tf(v.z); sA[row][c4+3] = f2tf(v.w);
            float4 w4 = *(const float4*)(W + (size_t)(f0 + row) * 64 + k0 + c4);
            sB[row][c4] = f2tf(w4.x); sB[row][c4+1] = f2tf(w4.y);
            sB[row][c4+2] = f2tf(w4.z); sB[row][c4+3] = f2tf(w4.w);
        }
        __syncthreads();
#pragma unroll
        for (int kk = 0; kk < 32; kk += 8) {
            unsigned af[4][4], bf[4][2];
#pragma unroll
            for (int mt = 0; mt < 4; mt++)
                ldsm4(af[mt], &sA[m0 + mt * 16 + arow][kk + acol4]);
#pragma unroll
            for (int np = 0; np < 2; np++) {
                unsigned d[4];
                ldsm4(d, &sB[n0 + np * 16 + arow][kk + acol4]);
                bf[np*2][0] = d[0]; bf[np*2+1][0] = d[1];
                bf[np*2][1] = d[2]; bf[np*2+1][1] = d[3];
            }
#pragma unroll
            for (int mt = 0; mt < 4; mt++)
#pragma unroll
                for (int nt = 0; nt < 4; nt++)
                    mma_tf32(acc[mt][nt], af[mt][0], af[mt][1], af[mt][2], af[mt][3],
                             bf[nt][0], bf[nt][1]);
        }
        __syncthreads();
    }

#pragma unroll
    for (int mt = 0; mt < 4; mt++) {
#pragma unroll
        for (int rr = 0; rr < 2; rr++) {
            size_t T = T0 + m0 + mt * 16 + r + rr * 8;
            int b = (int)(T >> 16);
            int s = (int)((T >> 8) & 255);
            int n = (int)(T & 255);
            int g = n >> 6;
            int h = (n >> 3) & 7;
            float ssq = 0.0f;
#pragma unroll
            for (int nt = 0; nt < 4; nt++) {
                int f = f0 + n0 + nt * 8 + 2 * cl;
                float2 bv = *(const float2*)(bias + f);
                float a0 = acc[mt][nt][rr*2]   + bv.x;
                float a1 = acc[mt][nt][rr*2+1] + bv.y;
                ssq += a0 * a0 + a1 * a1;
                int d0 = ((n & 7) << 8) + f;
                if (g < 2) {
                    // q or k: store packed bf16
                    size_t idx = (((size_t)(b * 8 + h) * 256 + s) << 11) + d0;
                    unsigned short* dst = (g == 0) ? g_qh : g_kh;
                    *(unsigned*)(dst + idx) = pack_bf16(a0, a1);
                } else {
                    float2 val;
                    val.x = __uint_as_float(f2tf(a0));
                    val.y = __uint_as_float(f2tf(a1));
                    float* dst; size_t idx;
                    if (g == 3) {
                        int h2 = s >> 5;
                        int s2 = h * 32 + (d0 >> 6);
                        int d2 = ((s & 31) << 6) + (d0 & 63);
                        dst = g_vV;
                        idx = (((size_t)(b * 8 + h2) * 256 + s2) << 11) + d2;
                    } else {
                        dst = g_vH;
                        idx = (((size_t)(b * 8 + h) * 256 + s) << 11) + d0;
                    }
                    *(float2*)(dst + idx) = val;
                }
            }
            if (g < 2) {
                ssq += __shfl_xor_sync(0xffffffffu, ssq, 1);
                ssq += __shfl_xor_sync(0xffffffffu, ssq, 2);
                if (cl == 0)
                    atomicAdd((g == 0 ? g_inq : g_ink) + (b * 8 + h) * 256 + s, ssq);
            }
        }
    }
}

// ---------------------------------------------------------------------------
// Kernel 2: fused sim + dual softmax, bf16 MMA (m16n8k16, 2x tf32 rate).
// Tile 128x256, grid (64,2), 512 threads. kc=128 double-buffered cp.async.
// smem: Q 2x128x136 b16 + K 2x256x136 b16 = 208896 B.
// ---------------------------------------------------------------------------
#define SQ(b,rr,cc) sbf[((b)*128 + (rr))*136 + (cc)]
#define SK(b,rr,cc) sbf[2*128*136 + ((b)*256 + (rr))*136 + (cc)]

__global__ __launch_bounds__(512, 1) void k_simsm(const float* __restrict__ t1p,
                                                  const float* __restrict__ t2p)
{
    extern __shared__ unsigned short sbf[];
    const int t = threadIdx.x;
    const int lane = t & 31, warp = t >> 5;
    const int m0 = (warp >> 2) * 32;
    const int nwarp = warp & 3;
    const int n0 = nwarp * 64;
    const int r = lane >> 2, cl = lane & 3;
    const int grp = lane >> 3, li = lane & 7;
    const int arow = (grp & 1) * 8 + li;
    const int acol8 = (grp >> 1) * 8;          // bf16 column offset
    const int bh = blockIdx.x, y = blockIdx.y;
    const unsigned short* Qb = g_qh + ((size_t)bh * 256 + y * 128) * 2048;
    const unsigned short* Kb = g_kh + (size_t)bh * 256 * 2048;

    float acc[2][8][4] = {};

    // chunk = 128 k. Q: 128 rows x 256B = 16 cpa16/row-set; per thread 4.
    // K: 256 rows x 256B; per thread 8.
    {
#pragma unroll
        for (int p = 0; p < 4; p++) {
            int lin = t + p * 512, row = lin >> 4, seg = lin & 15;
            cpa16(&SQ(0, row, seg * 8), Qb + (size_t)row * 2048 + seg * 8);
        }
#pragma unroll
        for (int p = 0; p < 8; p++) {
            int lin = t + p * 512, row = lin >> 4, seg = lin & 15;
            cpa16(&SK(0, row, seg * 8), Kb + (size_t)row * 2048 + seg * 8);
        }
        CP_COMMIT();
    }

    for (int ch = 0; ch < 16; ch++) {
        if (ch < 15) {
            int nb = (ch + 1) & 1, k0 = (ch + 1) * 128;
#pragma unroll
            for (int p = 0; p < 4; p++) {
                int lin = t + p * 512, row = lin >> 4, seg = lin & 15;
                cpa16(&SQ(nb, row, seg * 8), Qb + (size_t)row * 2048 + k0 + seg * 8);
            }
#pragma unroll
            for (int p = 0; p < 8; p++) {
                int lin = t + p * 512, row = lin >> 4, seg = lin & 15;
                cpa16(&SK(nb, row, seg * 8), Kb + (size_t)row * 2048 + k0 + seg * 8);
            }
            CP_COMMIT();
            CP_WAIT1();
        } else {
            CP_WAIT0();
        }
        __syncthreads();
        const int buf = ch & 1;
#pragma unroll
        for (int kk = 0; kk < 128; kk += 16) {
            unsigned af[2][4], bf[8][2];
#pragma unroll
            for (int mt = 0; mt < 2; mt++)
                ldsm4(af[mt], &SQ(buf, m0 + mt * 16 + arow, kk + acol8));
#pragma unroll
            for (int np = 0; np < 4; np++) {
                unsigned d[4];
                ldsm4(d, &SK(buf, n0 + np * 16 + arow, kk + acol8));
                bf[np*2][0] = d[0]; bf[np*2+1][0] = d[1];
                bf[np*2][1] = d[2]; bf[np*2+1][1] = d[3];
            }
#pragma unroll
            for (int mt = 0; mt < 2; mt++)
#pragma unroll
                for (int nt = 0; nt < 8; nt++)
                    mma_bf16(acc[mt][nt], af[mt][0], af[mt][1], af[mt][2], af[mt][3],
                             bf[nt][0], bf[nt][1]);
        }
        __syncthreads();
    }

    // ---------------- epilogue: scale + dual softmax ----------------
    const int h = bh & 7;
    const float T1 = t1p[h], T2 = t2p[h];
    const int rowbase = bh * 256 + y * 128;
    float* fsm = (float*)sbf;

    float iq[4];
#pragma unroll
    for (int i = 0; i < 4; i++) {
        float ssq = g_inq[rowbase + m0 + (i >> 1) * 16 + (i & 1) * 8 + r];
        iq[i] = 1.0f / fmaxf(sqrtf(ssq), 1e-12f);
    }
    float ikv[8][2];
#pragma unroll
    for (int nt = 0; nt < 8; nt++) {
        float2 v2 = *(const float2*)(g_ink + bh * 256 + n0 + nt * 8 + 2 * cl);
        ikv[nt][0] = 1.0f / fmaxf(sqrtf(v2.x), 1e-12f);
        ikv[nt][1] = 1.0f / fmaxf(sqrtf(v2.y), 1e-12f);
    }
#pragma unroll
    for (int mt = 0; mt < 2; mt++)
#pragma unroll
        for (int nt = 0; nt < 8; nt++)
#pragma unroll
            for (int rr = 0; rr < 2; rr++) {
                acc[mt][nt][rr*2]   *= iq[mt*2+rr] * ikv[nt][0];
                acc[mt][nt][rr*2+1] *= iq[mt*2+rr] * ikv[nt][1];
            }

    float mx[4], mn[4];
#pragma unroll
    for (int i = 0; i < 4; i++) { mx[i] = -3.0e38f; mn[i] = 3.0e38f; }
#pragma unroll
    for (int mt = 0; mt < 2; mt++)
#pragma unroll
        for (int rr = 0; rr < 2; rr++) {
            int i = mt * 2 + rr;
#pragma unroll
            for (int nt = 0; nt < 8; nt++) {
                mx[i] = fmaxf(mx[i], fmaxf(acc[mt][nt][rr*2], acc[mt][nt][rr*2+1]));
                mn[i] = fminf(mn[i], fminf(acc[mt][nt][rr*2], acc[mt][nt][rr*2+1]));
            }
        }
#pragma unroll
    for (int o = 1; o <= 2; o <<= 1)
#pragma unroll
        for (int i = 0; i < 4; i++) {
            mx[i] = fmaxf(mx[i], __shfl_xor_sync(0xffffffffu, mx[i], o));
            mn[i] = fminf(mn[i], __shfl_xor_sync(0xffffffffu, mn[i], o));
        }

    float* sMx = fsm;          // [128][4]
    float* sMn = fsm + 512;
    if (cl == 0) {
#pragma unroll
        for (int i = 0; i < 4; i++) {
            int lr = m0 + (i >> 1) * 16 + (i & 1) * 8 + r;
            sMx[lr * 4 + nwarp] = mx[i];
            sMn[lr * 4 + nwarp] = mn[i];
        }
    }
    __syncthreads();
    float M1[4], M2[4];
#pragma unroll
    for (int i = 0; i < 4; i++) {
        int lr = m0 + (i >> 1) * 16 + (i & 1) * 8 + r;
        float vmx = sMx[lr*4], vmn = sMn[lr*4];
#pragma unroll
        for (int k = 1; k < 4; k++) {
            vmx = fmaxf(vmx, sMx[lr*4+k]);
            vmn = fminf(vmn, sMn[lr*4+k]);
        }
        M1[i] = (T1 >= 0.0f) ? T1 * vmx : T1 * vmn;
        M2[i] = (T2 >= 0.0f) ? T2 * vmx : T2 * vmn;
    }

    float s1[4] = {}, s2[4] = {};
#pragma unroll
    for (int mt = 0; mt < 2; mt++)
#pragma unroll
        for (int rr = 0; rr < 2; rr++) {
            int i = mt * 2 + rr;
            int lr = m0 + mt * 16 + rr * 8 + r;
            size_t rowoff = (size_t)(rowbase + lr) * 256;
#pragma unroll
            for (int nt = 0; nt < 8; nt++) {
                int col = n0 + nt * 8 + 2 * cl;
                float v0 = acc[mt][nt][rr*2], v1 = acc[mt][nt][rr*2+1];
                float e10 = __expf(v0 * T1 - M1[i]);
                float e11 = __expf(v1 * T1 - M1[i]);
                float e20 = __expf(v0 * T2 - M2[i]);
                float e21 = __expf(v1 * T2 - M2[i]);
                s1[i] += e10 + e11;
                s2[i] += e20 + e21;
                float2 o1, o2;
                o1.x = __uint_as_float(f2tf(e10)); o1.y = __uint_as_float(f2tf(e11));
                o2.x = __uint_as_float(f2tf(e20)); o2.y = __uint_as_float(f2tf(e21));
                *(float2*)(g_aH + rowoff + col) = o1;
                *(float2*)(g_aV + rowoff + col) = o2;
            }
        }
#pragma unroll
    for (int o = 1; o <= 2; o <<= 1)
#pragma unroll
        for (int i = 0; i < 4; i++) {
            s1[i] += __shfl_xor_sync(0xffffffffu, s1[i], o);
            s2[i] += __shfl_xor_sync(0xffffffffu, s2[i], o);
        }
    __syncthreads();
    float* sS1 = fsm;
    float* sS2 = fsm + 512;
    if (cl == 0) {
#pragma unroll
        for (int i = 0; i < 4; i++) {
            int lr = m0 + (i >> 1) * 16 + (i & 1) * 8 + r;
            sS1[lr * 4 + nwarp] = s1[i];
            sS2[lr * 4 + nwarp] = s2[i];
        }
    }
    __syncthreads();
    if (nwarp == 0 && cl == 0) {
#pragma unroll
        for (int i = 0; i < 4; i++) {
            int lr = m0 + (i >> 1) * 16 + (i & 1) * 8 + r;
            float tt1 = sS1[lr*4] + sS1[lr*4+1] + sS1[lr*4+2] + sS1[lr*4+3];
            float tt2 = sS2[lr*4] + sS2[lr*4+1] + sS2[lr*4+2] + sS2[lr*4+3];
            g_rs1[rowbase + lr] = tt1;
            g_rs2[rowbase + lr] = tt2;
        }
    }
}

// ---------------------------------------------------------------------------
// Kernel 3: x = (E1 @ vH)/rs1 + (E2 @ vV)/rs2, then FUSED output projection.
// (unchanged from R9)
// ---------------------------------------------------------------------------
#define PVA(b,rr,cc) dsm[((b)*128 + (rr))*36 + (cc)]
#define PVB(b,rr,cc) dsm[2*128*36 + ((b)*32 + (rr))*136 + (cc)]
#define TOK(rr,cc)   dsm[(rr)*68 + (cc)]
#define WPS(rr,cc)   dsm[17408 + (rr)*68 + (cc)]

__global__ __launch_bounds__(256, 2) void k_pv(const float* __restrict__ Wp,
                                               const float* __restrict__ bp,
                                               float* __restrict__ out)
{
    extern __shared__ unsigned dsm[];
    const int t = threadIdx.x;
    const int lane = t & 31, warp = t >> 5;
    const int m0 = (warp >> 2) * 64, n0 = (warp & 3) * 32;
    const int r = lane >> 2, cl = lane & 3;
    const int grp = lane >> 3, li = lane & 7;
    const int arow = (grp & 1) * 8 + li;
    const int acol4 = (grp >> 1) * 4;
    const int bh = blockIdx.x, y = blockIdx.y, z = blockIdx.z;
    const int rowbase = bh * 256 + y * 128;

    float ratio[8];
#pragma unroll
    for (int i = 0; i < 8; i++) {
        int lr = m0 + (i >> 1) * 16 + (i & 1) * 8 + r;
        ratio[i] = __fdividef(g_rs2[rowbase + lr], g_rs1[rowbase + lr]);
    }

    float acc[4][4][4] = {};

    auto srcA = [&](int ch) -> const float* {
        return (ch < 8 ? g_aH : g_aV) + (size_t)rowbase * 256 + (ch & 7) * 32;
    };
    auto srcB = [&](int ch) -> const float* {
        return (ch < 8 ? g_vH : g_vV) + (size_t)bh * 524288
               + (size_t)((ch & 7) * 32) * 2048 + z * 128;
    };

    {
        const float* A = srcA(0); const float* Bp2 = srcB(0);
#pragma unroll
        for (int p = 0; p < 4; p++) {
            int lin = t + p * 256, row = lin >> 3, seg = lin & 7;
            cpa16(&PVA(0, row, seg * 4), A + (size_t)row * 256 + seg * 4);
        }
#pragma unroll
        for (int p = 0; p < 4; p++) {
            int lin = t + p * 256, row = lin >> 5, seg = lin & 31;
            cpa16(&PVB(0, row, seg * 4), Bp2 + (size_t)row * 2048 + seg * 4);
        }
        CP_COMMIT();
    }

    for (int ch = 0; ch < 16; ch++) {
        if (ch < 15) {
            int nb = (ch + 1) & 1;
            const float* A = srcA(ch + 1); const float* Bp2 = srcB(ch + 1);
#pragma unroll
            for (int p = 0; p < 4; p++) {
                int lin = t + p * 256, row = lin >> 3, seg = lin & 7;
                cpa16(&PVA(nb, row, seg * 4), A + (size_t)row * 256 + seg * 4);
            }
#pragma unroll
            for (int p = 0; p < 4; p++) {
                int lin = t + p * 256, row = lin >> 5, seg = lin & 31;
                cpa16(&PVB(nb, row, seg * 4), Bp2 + (size_t)row * 2048 + seg * 4);
            }
            CP_COMMIT();
            CP_WAIT1();
        } else {
            CP_WAIT0();
        }
        __syncthreads();
        const int buf = ch & 1;
#pragma unroll
        for (int kk = 0; kk < 32; kk += 8) {
            unsigned af[4][4], bf[4][2];
#pragma unroll
            for (int mt = 0; mt < 4; mt++)
                ldsm4(af[mt], &PVA(buf, m0 + mt * 16 + arow, kk + acol4));
#pragma unroll
            for (int nt = 0; nt < 4; nt++) {
                int nc = n0 + nt * 8 + r;
                bf[nt][0] = PVB(buf, kk+cl, nc); bf[nt][1] = PVB(buf, kk+cl+4, nc);
            }
#pragma unroll
            for (int mt = 0; mt < 4; mt++)
#pragma unroll
                for (int nt = 0; nt < 4; nt++)
                    mma_tf32(acc[mt][nt], af[mt][0], af[mt][1], af[mt][2], af[mt][3],
                             bf[nt][0], bf[nt][1]);
        }
        if (ch == 7) {
#pragma unroll
            for (int mt = 0; mt < 4; mt++)
#pragma unroll
                for (int rr = 0; rr < 2; rr++) {
                    float f = ratio[mt*2+rr];
#pragma unroll
                    for (int nt = 0; nt < 4; nt++) {
                        acc[mt][nt][rr*2]   *= f;
                        acc[mt][nt][rr*2+1] *= f;
                    }
                }
        }
        __syncthreads();
    }

    // -------- stage normalized x rows as 256 complete tokens + load Wp ------
    __syncthreads();
    const int half = (n0 >= 64) ? 1 : 0;
#pragma unroll
    for (int mt = 0; mt < 4; mt++) {
#pragma unroll
        for (int rr = 0; rr < 2; rr++) {
            int s_local = m0 + mt * 16 + rr * 8 + r;
            float f = __fdividef(1.0f, g_rs2[rowbase + s_local]);
            int tt = s_local * 2 + half;
#pragma unroll
            for (int nt = 0; nt < 4; nt++) {
                int c = ((n0 & 63) + nt * 8 + 2 * cl);
                TOK(tt, c)   = f2tf(acc[mt][nt][rr*2]   * f);
                TOK(tt, c+1) = f2tf(acc[mt][nt][rr*2+1] * f);
            }
        }
    }
    for (int i = t; i < 1024; i += 256) {
        int row = i >> 4, c4 = (i & 15) << 2;
        float4 w4 = *(const float4*)(Wp + (size_t)row * 64 + c4);
        WPS(row, c4) = f2tf(w4.x); WPS(row, c4+1) = f2tf(w4.y);
        WPS(row, c4+2) = f2tf(w4.z); WPS(row, c4+3) = f2tf(w4.w);
    }
    __syncthreads();

    // -------- fused projection: each warp projects 32 token rows ------------
    float acc2[2][8][4] = {};
    const int tt0 = warp * 32;
#pragma unroll
    for (int kk = 0; kk < 64; kk += 8) {
        unsigned af[2][4], bf[8][2];
#pragma unroll
        for (int mt = 0; mt < 2; mt++)
            ldsm4(af[mt], &TOK(tt0 + mt * 16 + arow, kk + acol4));
#pragma unroll
        for (int np = 0; np < 4; np++) {
            unsigned d[4];
            ldsm4(d, &WPS(np * 16 + arow, kk + acol4));
            bf[np*2][0] = d[0]; bf[np*2+1][0] = d[1];
            bf[np*2][1] = d[2]; bf[np*2+1][1] = d[3];
        }
#pragma unroll
        for (int mt = 0; mt < 2; mt++)
#pragma unroll
            for (int nt = 0; nt < 8; nt++)
                mma_tf32(acc2[mt][nt], af[mt][0], af[mt][1], af[mt][2], af[mt][3],
                         bf[nt][0], bf[nt][1]);
    }

    const int b = bh >> 3, h = bh & 7;
#pragma unroll
    for (int mt = 0; mt < 2; mt++) {
#pragma unroll
        for (int rr = 0; rr < 2; rr++) {
            int tt = tt0 + mt * 16 + rr * 8 + r;
            int s = y * 128 + (tt >> 1);
            int nn = h * 32 + 2 * z + (tt & 1);
            size_t rowoff = ((size_t)b * 65536 + (size_t)s * 256 + nn) * 64;
#pragma unroll
            for (int nt = 0; nt < 8; nt++) {
                int c = nt * 8 + 2 * cl;
                float2 bv = *(const float2*)(bp + c);
                float2 o;
                o.x = acc2[mt][nt][rr*2]   + bv.x;
                o.y = acc2[mt][nt][rr*2+1] + bv.y;
                *(float2*)(out + rowoff + c) = o;
            }
        }
    }
}

// ---------------------------------------------------------------------------
extern "C" void kernel_launch(void* const* d_in, const int* in_sizes, int n_in,
                              void* d_out, int out_size)
{
    const float* x      = (const float*)d_in[0];
    const float* qkv_w  = (const float*)d_in[1];
    const float* qkv_b  = (const float*)d_in[2];
    const float* proj_w = (const float*)d_in[3];
    const float* proj_b = (const float*)d_in[4];
    const float* t1     = (const float*)d_in[5];
    const float* t2     = (const float*)d_in[6];
    float* out          = (float*)d_out;

    cudaFuncSetAttribute(k_simsm, cudaFuncAttributeMaxDynamicSharedMemorySize, 208896);
    cudaFuncSetAttribute(k_pv,    cudaFuncAttributeMaxDynamicSharedMemorySize, 87040);

    k_zero<<<16, 1024>>>();
    k_qkv<<<dim3(4096, 2), 256>>>(x, qkv_w, qkv_b);
    k_simsm<<<dim3(64, 2), 512, 208896>>>(t1, t2);
    k_pv<<<dim3(64, 2, 16), 256, 87040>>>(proj_w, proj_b, out);
}